// round 1
// baseline (speedup 1.0000x reference)
#include <cuda_runtime.h>
#include <math.h>

#define BB   2
#define SS   2048
#define HH   2048
#define NHD  16
#define HDD  128
#define WW   512
#define BSZ  (BB*SS)          // 4096 rows

#define NEG_INF (__int_as_float(0xff800000u))

// -------- scratch (static device globals; no dynamic allocation) --------
__device__ float g_y [BSZ*HH];   // layernorm output           [BS, H]
__device__ float g_q [BSZ*HH];   // q (pre-scaled)             [B,NH,S,HD]
__device__ float g_k [BSZ*HH];   // k                          [B,NH,S,HD]
__device__ float g_v [BSZ*HH];   // v                          [B,NH,S,HD]
__device__ float g_ao[BSZ*HH];   // attention output           [B,S,NH,HD]

// ======================= LayerNorm =======================
__device__ __forceinline__ float block_sum_2048(float s) {
    __shared__ float ws[8];
    const int lane = threadIdx.x & 31, wid = threadIdx.x >> 5;
#pragma unroll
    for (int o = 16; o > 0; o >>= 1) s += __shfl_xor_sync(0xffffffffu, s, o);
    __syncthreads();                 // protect ws reuse across calls
    if (lane == 0) ws[wid] = s;
    __syncthreads();
    float t = ws[0];
#pragma unroll
    for (int i = 1; i < 8; i++) t += ws[i];
    return t;
}

__global__ void __launch_bounds__(256) ln_kernel(const float* __restrict__ x,
                                                 const float* __restrict__ gamma,
                                                 const float* __restrict__ beta,
                                                 float* __restrict__ y)
{
    const int row = blockIdx.x;          // 0..4095
    const int tid = threadIdx.x;         // 256 threads
    const float* xr = x + (size_t)row * HH;
    float v[8];
#pragma unroll
    for (int i = 0; i < 8; i++) v[i] = xr[tid + i * 256];
    float s = 0.f;
#pragma unroll
    for (int i = 0; i < 8; i++) s += v[i];
    const float mu = block_sum_2048(s) * (1.0f / HH);
    float sq = 0.f;
#pragma unroll
    for (int i = 0; i < 8; i++) { float d = v[i] - mu; sq += d * d; }
    const float var = block_sum_2048(sq) * (1.0f / HH);
    const float rs = rsqrtf(var + 1e-6f);
    float* yr = y + (size_t)row * HH;
#pragma unroll
    for (int i = 0; i < 8; i++) {
        const int c = tid + i * 256;
        yr[c] = (v[i] - mu) * rs * gamma[c] + beta[c];
    }
}

// ======================= GEMM: C = alpha*(A[4096,2048] @ B[2048,2048] + bias) =======================
// OUT_MODE 0: C row-major [M,N]   (O projection -> d_out)
// OUT_MODE 1: row=(b,s), col=(n,d) -> C[((b*NH+n)*S+s)*HD+d]   (QKV layout)
template<int OUT_MODE>
__global__ void __launch_bounds__(256) gemm_kernel(const float* __restrict__ A,
                                                   const float* __restrict__ Bw,
                                                   const float* __restrict__ bias,
                                                   float alpha,
                                                   float* __restrict__ C)
{
    constexpr int K = HH, N = HH;
    __shared__ float As[8][132];     // A^T slice, padded: conflict-free STS + LDS.128
    __shared__ float Bs[8][128];
    const int m0 = blockIdx.y * 128, n0 = blockIdx.x * 128;
    const int tid = threadIdx.x;
    const int tr = tid >> 4, tc = tid & 15;
    const int arow = tid >> 1, acol = (tid & 1) * 4;   // A tile 128x8
    const int brow = tid >> 5, bcol = (tid & 31) * 4;  // B tile 8x128
    const float* Ap = A + (size_t)(m0 + arow) * K + acol;
    const float* Bp = Bw + (size_t)brow * N + n0 + bcol;

    float acc[8][8];
#pragma unroll
    for (int i = 0; i < 8; i++)
#pragma unroll
        for (int j = 0; j < 8; j++) acc[i][j] = 0.f;

    float4 av = *(const float4*)(Ap);
    float4 bv = *(const float4*)(Bp);

    for (int k0 = 0; k0 < K; k0 += 8) {
        __syncthreads();
        As[acol + 0][arow] = av.x; As[acol + 1][arow] = av.y;
        As[acol + 2][arow] = av.z; As[acol + 3][arow] = av.w;
        *(float4*)&Bs[brow][bcol] = bv;
        // prefetch next chunk (hidden behind compute)
        if (k0 + 8 < K) {
            av = *(const float4*)(Ap + (k0 + 8));
            bv = *(const float4*)(Bp + (size_t)(k0 + 8) * N);
        }
        __syncthreads();
#pragma unroll
        for (int kk = 0; kk < 8; kk++) {
            float a[8] __align__(16), b[8] __align__(16);
            *(float4*)&a[0] = *(const float4*)&As[kk][tr * 4];
            *(float4*)&a[4] = *(const float4*)&As[kk][64 + tr * 4];
            *(float4*)&b[0] = *(const float4*)&Bs[kk][tc * 4];
            *(float4*)&b[4] = *(const float4*)&Bs[kk][64 + tc * 4];
#pragma unroll
            for (int i = 0; i < 8; i++)
#pragma unroll
                for (int j = 0; j < 8; j++) acc[i][j] = fmaf(a[i], b[j], acc[i][j]);
        }
    }

#pragma unroll
    for (int i = 0; i < 8; i++) {
        const int row = m0 + ((i < 4) ? tr * 4 + i : 64 + tr * 4 + i - 4);
#pragma unroll
        for (int jq = 0; jq < 2; jq++) {
            const int colb = n0 + ((jq == 0) ? tc * 4 : 64 + tc * 4);
            float4 outv;
            outv.x = alpha * (acc[i][jq * 4 + 0] + bias[colb + 0]);
            outv.y = alpha * (acc[i][jq * 4 + 1] + bias[colb + 1]);
            outv.z = alpha * (acc[i][jq * 4 + 2] + bias[colb + 2]);
            outv.w = alpha * (acc[i][jq * 4 + 3] + bias[colb + 3]);
            if (OUT_MODE == 0) {
                *(float4*)&C[(size_t)row * N + colb] = outv;
            } else {
                const int b = row >> 11, s = row & (SS - 1);
                const int n = colb >> 7, d = colb & (HDD - 1);
                *(float4*)&C[((size_t)((b * NHD + n) * SS + s)) * HDD + d] = outv;
            }
        }
    }
}

// ======================= Flash attention (complement-of-window mask) =======================
// masked (excluded) iff 0 <= qi - kj < W.  Fully-masked 128-tiles: i0 - j0 in {128,256,384}.
__global__ void __launch_bounds__(256) attn_kernel(float* __restrict__ aout)
{
    extern __shared__ float sm[];
    float* Qs  = sm;                 // [128][132]   natural (i,d)
    float* KVs = sm + 128 * 132;     // K^T as [d][j], later V as [j][d]
    float* Ps  = sm + 2 * 128 * 132; // [i][j]
    const int i0 = blockIdx.x * 128;
    const int n  = blockIdx.y;
    const int b  = blockIdx.z;
    const size_t hb = (size_t)(b * NHD + n) * SS * HDD;
    const float* qb = g_q + hb;
    const float* kb = g_k + hb;
    const float* vb = g_v + hb;
    const int tid = threadIdx.x;
    const int tr = tid >> 4, tc = tid & 15;
    const int r2 = tid >> 1, c2 = (tid & 1) * 4;
    const int ri0 = tr * 4, cj0 = tc * 4;

    // load Q tile (natural layout)
#pragma unroll
    for (int it = 0; it < 16; it++) {
        const int d = c2 + it * 8;
        *(float4*)&Qs[r2 * 132 + d] = *(const float4*)&qb[(size_t)(i0 + r2) * HDD + d];
    }

    float m_[8], l_[8], o_[8][8];
#pragma unroll
    for (int i = 0; i < 8; i++) { m_[i] = NEG_INF; l_[i] = 0.f; }
#pragma unroll
    for (int i = 0; i < 8; i++)
#pragma unroll
        for (int j = 0; j < 8; j++) o_[i][j] = 0.f;

    for (int jt = 0; jt < SS / 128; jt++) {
        const int j0 = jt * 128;
        const int diff = i0 - j0;
        if (diff == 128 || diff == 256 || diff == 384) continue;  // fully masked tile

        __syncthreads();   // prior PV reads of KVs done (also orders Q load on 1st iter)
        // load K transposed: KVs[d][j]
#pragma unroll
        for (int it = 0; it < 16; it++) {
            const int d = c2 + it * 8;
            const float4 kv = *(const float4*)&kb[(size_t)(j0 + r2) * HDD + d];
            KVs[(d + 0) * 132 + r2] = kv.x;
            KVs[(d + 1) * 132 + r2] = kv.y;
            KVs[(d + 2) * 132 + r2] = kv.z;
            KVs[(d + 3) * 132 + r2] = kv.w;
        }
        __syncthreads();

        // scores: sc[ii][jj] = sum_d Q[i][d] * K[j][d]
        float sc[8][8];
#pragma unroll
        for (int i = 0; i < 8; i++)
#pragma unroll
            for (int j = 0; j < 8; j++) sc[i][j] = 0.f;

        for (int d = 0; d < HDD; d += 4) {
            float a[8][4] __align__(16);
#pragma unroll
            for (int ii = 0; ii < 8; ii++) {
                const int r = (ii < 4) ? ri0 + ii : 64 + ri0 + ii - 4;
                *(float4*)&a[ii][0] = *(const float4*)&Qs[r * 132 + d];  // broadcast
            }
#pragma unroll
            for (int dd = 0; dd < 4; dd++) {
                float bj[8] __align__(16);
                *(float4*)&bj[0] = *(const float4*)&KVs[(d + dd) * 132 + cj0];
                *(float4*)&bj[4] = *(const float4*)&KVs[(d + dd) * 132 + 64 + cj0];
#pragma unroll
                for (int ii = 0; ii < 8; ii++)
#pragma unroll
                    for (int jj = 0; jj < 8; jj++)
                        sc[ii][jj] = fmaf(a[ii][dd], bj[jj], sc[ii][jj]);
            }
        }

        // mask + online softmax (rows owned by tr; reduce across the 16 tc lanes)
#pragma unroll
        for (int ii = 0; ii < 8; ii++) {
            const int qi = i0 + ((ii < 4) ? ri0 + ii : 64 + ri0 + ii - 4);
            float rmax = NEG_INF;
#pragma unroll
            for (int jj = 0; jj < 8; jj++) {
                const int kj = j0 + ((jj < 4) ? cj0 + jj : 64 + cj0 + jj - 4);
                const int dl = qi - kj;
                if (dl >= 0 && dl < WW) sc[ii][jj] = NEG_INF;   // in-window -> EXCLUDED
                rmax = fmaxf(rmax, sc[ii][jj]);
            }
#pragma unroll
            for (int o = 8; o > 0; o >>= 1)
                rmax = fmaxf(rmax, __shfl_xor_sync(0xffffffffu, rmax, o));
            const float mo = m_[ii];
            const float mn = fmaxf(mo, rmax);
            const float corr = (mo == mn) ? 1.f : __expf(mo - mn);  // handles -inf==-inf
            float rsum = 0.f;
#pragma unroll
            for (int jj = 0; jj < 8; jj++) {
                const float sv = sc[ii][jj];
                const float p = (sv == NEG_INF) ? 0.f : __expf(sv - mn);
                sc[ii][jj] = p;
                rsum += p;
            }
#pragma unroll
            for (int o = 8; o > 0; o >>= 1)
                rsum += __shfl_xor_sync(0xffffffffu, rsum, o);
            l_[ii] = l_[ii] * corr + rsum;
            m_[ii] = mn;
#pragma unroll
            for (int dd = 0; dd < 8; dd++) o_[ii][dd] *= corr;
        }

        // write P (natural [i][j]) — vectorized, conflict-free
#pragma unroll
        for (int ii = 0; ii < 8; ii++) {
            const int r = (ii < 4) ? ri0 + ii : 64 + ri0 + ii - 4;
            *(float4*)&Ps[r * 132 + cj0]      = make_float4(sc[ii][0], sc[ii][1], sc[ii][2], sc[ii][3]);
            *(float4*)&Ps[r * 132 + 64 + cj0] = make_float4(sc[ii][4], sc[ii][5], sc[ii][6], sc[ii][7]);
        }
        __syncthreads();   // P visible; K^T no longer needed

        // load V (natural [j][d]) into same buffer
#pragma unroll
        for (int it = 0; it < 16; it++) {
            const int d = c2 + it * 8;
            *(float4*)&KVs[r2 * 132 + d] = *(const float4*)&vb[(size_t)(j0 + r2) * HDD + d];
        }
        __syncthreads();

        // O += P @ V
        for (int j = 0; j < 128; j += 4) {
            float a[8][4] __align__(16);
#pragma unroll
            for (int ii = 0; ii < 8; ii++) {
                const int r = (ii < 4) ? ri0 + ii : 64 + ri0 + ii - 4;
                *(float4*)&a[ii][0] = *(const float4*)&Ps[r * 132 + j];  // broadcast
            }
#pragma unroll
            for (int jj = 0; jj < 4; jj++) {
                float bv[8] __align__(16);
                *(float4*)&bv[0] = *(const float4*)&KVs[(j + jj) * 132 + cj0];
                *(float4*)&bv[4] = *(const float4*)&KVs[(j + jj) * 132 + 64 + cj0];
#pragma unroll
                for (int ii = 0; ii < 8; ii++)
#pragma unroll
                    for (int dd = 0; dd < 8; dd++)
                        o_[ii][dd] = fmaf(a[ii][jj], bv[dd], o_[ii][dd]);
            }
        }
    }

    // normalize and write attn output in [B,S,NH,HD] (row-major for O projection)
#pragma unroll
    for (int ii = 0; ii < 8; ii++) {
        const int r = (ii < 4) ? ri0 + ii : 64 + ri0 + ii - 4;
        const float inv = 1.f / l_[ii];
        const size_t base = ((size_t)(b * SS + i0 + r) * NHD + n) * HDD;
        float4 o0 = make_float4(o_[ii][0] * inv, o_[ii][1] * inv, o_[ii][2] * inv, o_[ii][3] * inv);
        float4 o1 = make_float4(o_[ii][4] * inv, o_[ii][5] * inv, o_[ii][6] * inv, o_[ii][7] * inv);
        *(float4*)&aout[base + cj0]      = o0;
        *(float4*)&aout[base + 64 + cj0] = o1;
    }
}

// ======================= launch =======================
extern "C" void kernel_launch(void* const* d_in, const int* in_sizes, int n_in,
                              void* d_out, int out_size)
{
    (void)in_sizes; (void)n_in; (void)out_size;
    const float* x   = (const float*)d_in[0];
    const float* lns = (const float*)d_in[1];
    const float* lnb = (const float*)d_in[2];
    const float* wq  = (const float*)d_in[3];
    const float* bq  = (const float*)d_in[4];
    const float* wk  = (const float*)d_in[5];
    const float* bk  = (const float*)d_in[6];
    const float* wv  = (const float*)d_in[7];
    const float* bv  = (const float*)d_in[8];
    const float* wo  = (const float*)d_in[9];
    const float* bo  = (const float*)d_in[10];
    float* out = (float*)d_out;

    float *py, *pq, *pk, *pv, *pa;
    cudaGetSymbolAddress((void**)&py, g_y);
    cudaGetSymbolAddress((void**)&pq, g_q);
    cudaGetSymbolAddress((void**)&pk, g_k);
    cudaGetSymbolAddress((void**)&pv, g_v);
    cudaGetSymbolAddress((void**)&pa, g_ao);

    ln_kernel<<<BSZ, 256>>>(x, lns, lnb, py);

    dim3 gg(HH / 128, BSZ / 128);
    const float qscale = 0.08838834764831845f;   // 1/sqrt(128)
    gemm_kernel<1><<<gg, 256>>>(py, wq, bq, qscale, pq);
    gemm_kernel<1><<<gg, 256>>>(py, wk, bk, 1.f, pk);
    gemm_kernel<1><<<gg, 256>>>(py, wv, bv, 1.f, pv);

    const int attn_smem = 3 * 128 * 132 * 4;     // 202752 B
    cudaFuncSetAttribute(attn_kernel, cudaFuncAttributeMaxDynamicSharedMemorySize, attn_smem);
    attn_kernel<<<dim3(SS / 128, NHD, BB), 256, attn_smem>>>(pa);

    gemm_kernel<0><<<gg, 256>>>(pa, wo, bo, 1.f, out);
}

// round 3
// speedup vs baseline: 1.3421x; 1.3421x over previous
#include <cuda_runtime.h>
#include <cuda_bf16.h>
#include <math.h>
#include <stdint.h>

#define BB   2
#define SS   2048
#define HH   2048
#define NHD  16
#define HDD  128
#define WW   512
#define BSZ  (BB*SS)          // 4096 rows

#define NEG_INF (__int_as_float(0xff800000u))

// -------- scratch (static device globals; no dynamic allocation) --------
__device__ __nv_bfloat16 g_yh [BSZ*HH];   // layernorm out, hi
__device__ __nv_bfloat16 g_yl [BSZ*HH];   // layernorm out, lo
__device__ __nv_bfloat16 g_wqh[HH*HH], g_wql[HH*HH];
__device__ __nv_bfloat16 g_wkh[HH*HH], g_wkl[HH*HH];
__device__ __nv_bfloat16 g_wvh[HH*HH], g_wvl[HH*HH];
__device__ __nv_bfloat16 g_woh[HH*HH], g_wol[HH*HH];
__device__ float g_q [BSZ*HH];   // q (pre-scaled)  [B,NH,S,HD]
__device__ float g_k [BSZ*HH];   // k               [B,NH,S,HD]
__device__ float g_v [BSZ*HH];   // v               [B,NH,S,HD]
__device__ __nv_bfloat16 g_aoh[BSZ*HH];   // attn out hi  [B,S,NH,HD]
__device__ __nv_bfloat16 g_aol[BSZ*HH];   // attn out lo

// ======================= PTX helpers (compute_100-safe only) =======================
__device__ __forceinline__ uint32_t smem_u32(const void* p) {
    uint32_t a;
    asm("{ .reg .u64 t; cvta.to.shared.u64 t, %1; cvt.u32.u64 %0, t; }" : "=r"(a) : "l"(p));
    return a;
}

__device__ __forceinline__ void cp_async16(uint32_t saddr, const void* gptr) {
    asm volatile("cp.async.cg.shared.global [%0], [%1], 16;" :: "r"(saddr), "l"(gptr));
}
__device__ __forceinline__ void cp_commit() { asm volatile("cp.async.commit_group;"); }
template<int N>
__device__ __forceinline__ void cp_wait() { asm volatile("cp.async.wait_group %0;" :: "n"(N)); }

__device__ __forceinline__ void ldm_x4(uint32_t& r0, uint32_t& r1, uint32_t& r2, uint32_t& r3,
                                       uint32_t addr) {
    asm volatile("ldmatrix.sync.aligned.m8n8.x4.shared.b16 {%0,%1,%2,%3}, [%4];"
                 : "=r"(r0), "=r"(r1), "=r"(r2), "=r"(r3) : "r"(addr));
}

__device__ __forceinline__ void mma16816(float* c, const uint32_t* a, const uint32_t* b) {
    asm volatile("mma.sync.aligned.m16n8k16.row.col.f32.bf16.bf16.f32 "
                 "{%0,%1,%2,%3}, {%4,%5,%6,%7}, {%8,%9}, {%0,%1,%2,%3};"
                 : "+f"(c[0]), "+f"(c[1]), "+f"(c[2]), "+f"(c[3])
                 : "r"(a[0]), "r"(a[1]), "r"(a[2]), "r"(a[3]), "r"(b[0]), "r"(b[1]));
}

// ======================= LayerNorm (emits bf16 hi/lo split) =======================
__device__ __forceinline__ float block_sum_2048(float s) {
    __shared__ float ws[8];
    const int lane = threadIdx.x & 31, wid = threadIdx.x >> 5;
#pragma unroll
    for (int o = 16; o > 0; o >>= 1) s += __shfl_xor_sync(0xffffffffu, s, o);
    __syncthreads();
    if (lane == 0) ws[wid] = s;
    __syncthreads();
    float t = ws[0];
#pragma unroll
    for (int i = 1; i < 8; i++) t += ws[i];
    return t;
}

__global__ void __launch_bounds__(256) ln_kernel(const float* __restrict__ x,
                                                 const float* __restrict__ gamma,
                                                 const float* __restrict__ beta,
                                                 __nv_bfloat16* __restrict__ yh,
                                                 __nv_bfloat16* __restrict__ yl)
{
    const int row = blockIdx.x;
    const int tid = threadIdx.x;
    const float* xr = x + (size_t)row * HH;
    float v[8];
#pragma unroll
    for (int i = 0; i < 8; i++) v[i] = xr[tid + i * 256];
    float s = 0.f;
#pragma unroll
    for (int i = 0; i < 8; i++) s += v[i];
    const float mu = block_sum_2048(s) * (1.0f / HH);
    float sq = 0.f;
#pragma unroll
    for (int i = 0; i < 8; i++) { float d = v[i] - mu; sq += d * d; }
    const float var = block_sum_2048(sq) * (1.0f / HH);
    const float rs = rsqrtf(var + 1e-6f);
#pragma unroll
    for (int i = 0; i < 8; i++) {
        const int c = tid + i * 256;
        const float val = (v[i] - mu) * rs * gamma[c] + beta[c];
        const __nv_bfloat16 h = __float2bfloat16(val);
        yh[(size_t)row * HH + c] = h;
        yl[(size_t)row * HH + c] = __float2bfloat16(val - __bfloat162float(h));
    }
}

// ======================= Weight transpose + bf16 split: W[K][N] -> Wh/Wl[N][K] =======================
__global__ void __launch_bounds__(256) wsplit_kernel(const float* __restrict__ W,
                                                     __nv_bfloat16* __restrict__ Wh,
                                                     __nv_bfloat16* __restrict__ Wl)
{
    __shared__ float t[32][33];
    const int tx = threadIdx.x & 31, ty = threadIdx.x >> 5;
    const int n = blockIdx.x * 32 + tx;
#pragma unroll
    for (int i = 0; i < 4; i++) {
        const int k = blockIdx.y * 32 + ty + i * 8;
        t[ty + i * 8][tx] = W[(size_t)k * HH + n];
    }
    __syncthreads();
#pragma unroll
    for (int i = 0; i < 4; i++) {
        const int nn = blockIdx.x * 32 + ty + i * 8;
        const int kk = blockIdx.y * 32 + tx;
        const float v = t[tx][ty + i * 8];
        const __nv_bfloat16 h = __float2bfloat16(v);
        Wh[(size_t)nn * HH + kk] = h;
        Wl[(size_t)nn * HH + kk] = __float2bfloat16(v - __bfloat162float(h));
    }
}

// ======================= mma.sync GEMM: C[4096,2048] = alpha*(A @ B^T + bias) =======================
// A (hi/lo) [M,K] K-major bf16; B (hi/lo) [N,K] K-major bf16 (transposed weight).
// Tile 128x128, BK=32, 8 warps (4m x 2n), warp tile 32x64. 2-stage cp.async pipeline.
// SMEM row stride 40 bf16 (80 B) -> conflict-free ldmatrix.
#define GP_ROWB   80                    // bytes per smem row (32 bf16 data + pad)
#define GP_MAT    (128 * GP_ROWB)       // 10240 B per matrix
#define GP_STAGE  (4 * GP_MAT)          // Ah, Al, Bh, Bl = 40960 B
#define GP_SMEM   (2 * GP_STAGE)        // 81920 B

__device__ __forceinline__ void gemm_load_chunk(
    uint32_t sstage, int k0, int m0, int n0, int tid,
    const __nv_bfloat16* __restrict__ Ah, const __nv_bfloat16* __restrict__ Al,
    const __nv_bfloat16* __restrict__ Bh, const __nv_bfloat16* __restrict__ Bl)
{
#pragma unroll
    for (int mat = 0; mat < 4; ++mat) {
        const __nv_bfloat16* src = (mat == 0) ? Ah : (mat == 1) ? Al : (mat == 2) ? Bh : Bl;
        const int gbase = (mat < 2) ? m0 : n0;
        const uint32_t sb = sstage + mat * GP_MAT;
#pragma unroll
        for (int j = 0; j < 2; ++j) {
            const int idx = tid + j * 256;       // 0..511
            const int row = idx >> 2, c16 = idx & 3;
            cp_async16(sb + row * GP_ROWB + c16 * 16,
                       src + (size_t)(gbase + row) * HH + k0 + c16 * 8);
        }
    }
    cp_commit();
}

template<int OUT_MODE>  // 0: row-major [M,N] -> C;  1: QKV scatter [B,NH,S,HD]
__global__ void __launch_bounds__(256, 1) gemm_mma(
    const __nv_bfloat16* __restrict__ Ah, const __nv_bfloat16* __restrict__ Al,
    const __nv_bfloat16* __restrict__ Bh, const __nv_bfloat16* __restrict__ Bl,
    const float* __restrict__ bias, float alpha, float* __restrict__ C)
{
    extern __shared__ char sm8[];
    const uint32_t sbase = smem_u32(sm8);
    const int tid = threadIdx.x;
    const int wid = tid >> 5, lane = tid & 31;
    const int m0 = blockIdx.y * 128, n0 = blockIdx.x * 128;
    const int m_w = (wid >> 1) * 32, n_w = (wid & 1) * 64;

    float acc[2][8][4];
#pragma unroll
    for (int i = 0; i < 2; i++)
#pragma unroll
        for (int j = 0; j < 8; j++)
#pragma unroll
            for (int q = 0; q < 4; q++) acc[i][j][q] = 0.f;

    gemm_load_chunk(sbase, 0, m0, n0, tid, Ah, Al, Bh, Bl);

    const int arow = lane & 15, khalf = (lane >> 4) * 8;   // ldmatrix lane addressing

    for (int kc = 0; kc < HH / 32; ++kc) {
        if (kc + 1 < HH / 32) {
            gemm_load_chunk(sbase + ((kc + 1) & 1) * GP_STAGE, (kc + 1) * 32, m0, n0, tid,
                            Ah, Al, Bh, Bl);
            cp_wait<1>();
        } else {
            cp_wait<0>();
        }
        __syncthreads();

        const uint32_t st = sbase + (kc & 1) * GP_STAGE;
#pragma unroll
        for (int ks = 0; ks < 2; ++ks) {
            const int kb = (ks * 16 + khalf) * 2;   // byte col offset
            uint32_t ah[2][4], al[2][4];
#pragma unroll
            for (int mi = 0; mi < 2; ++mi) {
                const uint32_t roff = (m_w + mi * 16 + arow) * GP_ROWB + kb;
                ldm_x4(ah[mi][0], ah[mi][1], ah[mi][2], ah[mi][3], st + 0 * GP_MAT + roff);
                ldm_x4(al[mi][0], al[mi][1], al[mi][2], al[mi][3], st + 1 * GP_MAT + roff);
            }
            uint32_t bh[8][2], bl[8][2];
#pragma unroll
            for (int nf = 0; nf < 4; ++nf) {
                const uint32_t roff = (n_w + nf * 16 + arow) * GP_ROWB + kb;
                uint32_t r0, r1, r2, r3;
                ldm_x4(r0, r1, r2, r3, st + 2 * GP_MAT + roff);
                bh[2 * nf][0] = r0; bh[2 * nf][1] = r2;
                bh[2 * nf + 1][0] = r1; bh[2 * nf + 1][1] = r3;
                ldm_x4(r0, r1, r2, r3, st + 3 * GP_MAT + roff);
                bl[2 * nf][0] = r0; bl[2 * nf][1] = r2;
                bl[2 * nf + 1][0] = r1; bl[2 * nf + 1][1] = r3;
            }
#pragma unroll
            for (int mi = 0; mi < 2; ++mi)
#pragma unroll
                for (int nj = 0; nj < 8; ++nj) {
                    mma16816(acc[mi][nj], ah[mi], bh[nj]);
                    mma16816(acc[mi][nj], ah[mi], bl[nj]);
                    mma16816(acc[mi][nj], al[mi], bh[nj]);
                }
        }
        __syncthreads();
    }

    // epilogue: c0,c1 -> row g, cols 2*(lane&3)+{0,1}; c2,c3 -> row g+8
    const int g = lane >> 2, qn = (lane & 3) * 2;
#pragma unroll
    for (int mi = 0; mi < 2; ++mi) {
#pragma unroll
        for (int h = 0; h < 2; ++h) {
            const int row = m0 + m_w + mi * 16 + g + h * 8;
            float* dst;
            if (OUT_MODE == 0) {
                dst = C + (size_t)row * HH + n0;
            } else {
                const int b_ = row >> 11, s_ = row & (SS - 1);
                dst = C + ((size_t)((b_ * NHD + blockIdx.x) * SS + s_)) * HDD;
            }
#pragma unroll
            for (int nf = 0; nf < 8; ++nf) {
                const int col = n_w + nf * 8 + qn;
                float2 ov;
                ov.x = alpha * (acc[mi][nf][h * 2 + 0] + bias[n0 + col]);
                ov.y = alpha * (acc[mi][nf][h * 2 + 1] + bias[n0 + col + 1]);
                *(float2*)(dst + col) = ov;
            }
        }
    }
}

// ======================= Flash attention (complement-of-window mask) =======================
// masked (excluded) iff 0 <= qi - kj < W.  Fully-masked 128-tiles: i0 - j0 in {128,256,384}.
__global__ void __launch_bounds__(256) attn_kernel()
{
    extern __shared__ float sm[];
    float* Qs  = sm;
    float* KVs = sm + 128 * 132;
    float* Ps  = sm + 2 * 128 * 132;
    const int i0 = blockIdx.x * 128;
    const int n  = blockIdx.y;
    const int b  = blockIdx.z;
    const size_t hb = (size_t)(b * NHD + n) * SS * HDD;
    const float* qb = g_q + hb;
    const float* kb = g_k + hb;
    const float* vb = g_v + hb;
    const int tid = threadIdx.x;
    const int tr = tid >> 4, tc = tid & 15;
    const int r2 = tid >> 1, c2 = (tid & 1) * 4;
    const int ri0 = tr * 4, cj0 = tc * 4;

#pragma unroll
    for (int it = 0; it < 16; it++) {
        const int d = c2 + it * 8;
        *(float4*)&Qs[r2 * 132 + d] = *(const float4*)&qb[(size_t)(i0 + r2) * HDD + d];
    }

    float m_[8], l_[8], o_[8][8];
#pragma unroll
    for (int i = 0; i < 8; i++) { m_[i] = NEG_INF; l_[i] = 0.f; }
#pragma unroll
    for (int i = 0; i < 8; i++)
#pragma unroll
        for (int j = 0; j < 8; j++) o_[i][j] = 0.f;

    for (int jt = 0; jt < SS / 128; jt++) {
        const int j0 = jt * 128;
        const int diff = i0 - j0;
        if (diff == 128 || diff == 256 || diff == 384) continue;

        __syncthreads();
#pragma unroll
        for (int it = 0; it < 16; it++) {
            const int d = c2 + it * 8;
            const float4 kv = *(const float4*)&kb[(size_t)(j0 + r2) * HDD + d];
            KVs[(d + 0) * 132 + r2] = kv.x;
            KVs[(d + 1) * 132 + r2] = kv.y;
            KVs[(d + 2) * 132 + r2] = kv.z;
            KVs[(d + 3) * 132 + r2] = kv.w;
        }
        __syncthreads();

        float sc[8][8];
#pragma unroll
        for (int i = 0; i < 8; i++)
#pragma unroll
            for (int j = 0; j < 8; j++) sc[i][j] = 0.f;

        for (int d = 0; d < HDD; d += 4) {
            float a[8][4] __align__(16);
#pragma unroll
            for (int ii = 0; ii < 8; ii++) {
                const int r = (ii < 4) ? ri0 + ii : 64 + ri0 + ii - 4;
                *(float4*)&a[ii][0] = *(const float4*)&Qs[r * 132 + d];
            }
#pragma unroll
            for (int dd = 0; dd < 4; dd++) {
                float bj[8] __align__(16);
                *(float4*)&bj[0] = *(const float4*)&KVs[(d + dd) * 132 + cj0];
                *(float4*)&bj[4] = *(const float4*)&KVs[(d + dd) * 132 + 64 + cj0];
#pragma unroll
                for (int ii = 0; ii < 8; ii++)
#pragma unroll
                    for (int jj = 0; jj < 8; jj++)
                        sc[ii][jj] = fmaf(a[ii][dd], bj[jj], sc[ii][jj]);
            }
        }

#pragma unroll
        for (int ii = 0; ii < 8; ii++) {
            const int qi = i0 + ((ii < 4) ? ri0 + ii : 64 + ri0 + ii - 4);
            float rmax = NEG_INF;
#pragma unroll
            for (int jj = 0; jj < 8; jj++) {
                const int kj = j0 + ((jj < 4) ? cj0 + jj : 64 + cj0 + jj - 4);
                const int dl = qi - kj;
                if (dl >= 0 && dl < WW) sc[ii][jj] = NEG_INF;
                rmax = fmaxf(rmax, sc[ii][jj]);
            }
#pragma unroll
            for (int o = 8; o > 0; o >>= 1)
                rmax = fmaxf(rmax, __shfl_xor_sync(0xffffffffu, rmax, o));
            const float mo = m_[ii];
            const float mn = fmaxf(mo, rmax);
            const float corr = (mo == mn) ? 1.f : __expf(mo - mn);
            float rsum = 0.f;
#pragma unroll
            for (int jj = 0; jj < 8; jj++) {
                const float sv = sc[ii][jj];
                const float p = (sv == NEG_INF) ? 0.f : __expf(sv - mn);
                sc[ii][jj] = p;
                rsum += p;
            }
#pragma unroll
            for (int o = 8; o > 0; o >>= 1)
                rsum += __shfl_xor_sync(0xffffffffu, rsum, o);
            l_[ii] = l_[ii] * corr + rsum;
            m_[ii] = mn;
#pragma unroll
            for (int dd = 0; dd < 8; dd++) o_[ii][dd] *= corr;
        }

#pragma unroll
        for (int ii = 0; ii < 8; ii++) {
            const int r = (ii < 4) ? ri0 + ii : 64 + ri0 + ii - 4;
            *(float4*)&Ps[r * 132 + cj0]      = make_float4(sc[ii][0], sc[ii][1], sc[ii][2], sc[ii][3]);
            *(float4*)&Ps[r * 132 + 64 + cj0] = make_float4(sc[ii][4], sc[ii][5], sc[ii][6], sc[ii][7]);
        }
        __syncthreads();

#pragma unroll
        for (int it = 0; it < 16; it++) {
            const int d = c2 + it * 8;
            *(float4*)&KVs[r2 * 132 + d] = *(const float4*)&vb[(size_t)(j0 + r2) * HDD + d];
        }
        __syncthreads();

        for (int j = 0; j < 128; j += 4) {
            float a[8][4] __align__(16);
#pragma unroll
            for (int ii = 0; ii < 8; ii++) {
                const int r = (ii < 4) ? ri0 + ii : 64 + ri0 + ii - 4;
                *(float4*)&a[ii][0] = *(const float4*)&Ps[r * 132 + j];
            }
#pragma unroll
            for (int jj = 0; jj < 4; jj++) {
                float bv[8] __align__(16);
                *(float4*)&bv[0] = *(const float4*)&KVs[(j + jj) * 132 + cj0];
                *(float4*)&bv[4] = *(const float4*)&KVs[(j + jj) * 132 + 64 + cj0];
#pragma unroll
                for (int ii = 0; ii < 8; ii++)
#pragma unroll
                    for (int dd = 0; dd < 8; dd++)
                        o_[ii][dd] = fmaf(a[ii][jj], bv[dd], o_[ii][dd]);
            }
        }
    }

    // epilogue: normalize and write bf16 hi/lo split in [B,S,NH,HD] row-major
#pragma unroll
    for (int ii = 0; ii < 8; ii++) {
        const int r = (ii < 4) ? ri0 + ii : 64 + ri0 + ii - 4;
        const float inv = 1.f / l_[ii];
        const size_t base = ((size_t)(b * SS + i0 + r) * NHD + n) * HDD;
#pragma unroll
        for (int g = 0; g < 2; g++) {
            const int col = (g == 0) ? cj0 : 64 + cj0;
#pragma unroll
            for (int q = 0; q < 4; q++) {
                const float f = o_[ii][g * 4 + q] * inv;
                const __nv_bfloat16 h = __float2bfloat16(f);
                g_aoh[base + col + q] = h;
                g_aol[base + col + q] = __float2bfloat16(f - __bfloat162float(h));
            }
        }
    }
}

// ======================= launch =======================
extern "C" void kernel_launch(void* const* d_in, const int* in_sizes, int n_in,
                              void* d_out, int out_size)
{
    (void)in_sizes; (void)n_in; (void)out_size;
    const float* x   = (const float*)d_in[0];
    const float* lns = (const float*)d_in[1];
    const float* lnb = (const float*)d_in[2];
    const float* wq  = (const float*)d_in[3];
    const float* bq  = (const float*)d_in[4];
    const float* wk  = (const float*)d_in[5];
    const float* bk  = (const float*)d_in[6];
    const float* wv  = (const float*)d_in[7];
    const float* bv  = (const float*)d_in[8];
    const float* wo  = (const float*)d_in[9];
    const float* bo  = (const float*)d_in[10];
    float* out = (float*)d_out;

    __nv_bfloat16 *pyh, *pyl, *pwqh, *pwql, *pwkh, *pwkl, *pwvh, *pwvl, *pwoh, *pwol, *paoh, *paol;
    float *pq, *pk, *pv;
    cudaGetSymbolAddress((void**)&pyh, g_yh);   cudaGetSymbolAddress((void**)&pyl, g_yl);
    cudaGetSymbolAddress((void**)&pwqh, g_wqh); cudaGetSymbolAddress((void**)&pwql, g_wql);
    cudaGetSymbolAddress((void**)&pwkh, g_wkh); cudaGetSymbolAddress((void**)&pwkl, g_wkl);
    cudaGetSymbolAddress((void**)&pwvh, g_wvh); cudaGetSymbolAddress((void**)&pwvl, g_wvl);
    cudaGetSymbolAddress((void**)&pwoh, g_woh); cudaGetSymbolAddress((void**)&pwol, g_wol);
    cudaGetSymbolAddress((void**)&paoh, g_aoh); cudaGetSymbolAddress((void**)&paol, g_aol);
    cudaGetSymbolAddress((void**)&pq, g_q);
    cudaGetSymbolAddress((void**)&pk, g_k);
    cudaGetSymbolAddress((void**)&pv, g_v);

    ln_kernel<<<BSZ, 256>>>(x, lns, lnb, pyh, pyl);

    dim3 wg(HH / 32, HH / 32);
    wsplit_kernel<<<wg, 256>>>(wq, pwqh, pwql);
    wsplit_kernel<<<wg, 256>>>(wk, pwkh, pwkl);
    wsplit_kernel<<<wg, 256>>>(wv, pwvh, pwvl);
    wsplit_kernel<<<wg, 256>>>(wo, pwoh, pwol);

    cudaFuncSetAttribute(gemm_mma<0>, cudaFuncAttributeMaxDynamicSharedMemorySize, GP_SMEM);
    cudaFuncSetAttribute(gemm_mma<1>, cudaFuncAttributeMaxDynamicSharedMemorySize, GP_SMEM);

    dim3 gg(HH / 128, BSZ / 128);   // (16, 32)
    const float qscale = 0.08838834764831845f;   // 1/sqrt(128)
    gemm_mma<1><<<gg, 256, GP_SMEM>>>(pyh, pyl, pwqh, pwql, bq, qscale, pq);
    gemm_mma<1><<<gg, 256, GP_SMEM>>>(pyh, pyl, pwkh, pwkl, bk, 1.f, pk);
    gemm_mma<1><<<gg, 256, GP_SMEM>>>(pyh, pyl, pwvh, pwvl, bv, 1.f, pv);

    const int attn_smem = 3 * 128 * 132 * 4;     // 202752 B
    cudaFuncSetAttribute(attn_kernel, cudaFuncAttributeMaxDynamicSharedMemorySize, attn_smem);
    attn_kernel<<<dim3(SS / 128, NHD, BB), 256, attn_smem>>>();

    gemm_mma<0><<<gg, 256, GP_SMEM>>>(paoh, paol, pwoh, pwol, bo, 1.f, out);
}

// round 4
// speedup vs baseline: 2.0616x; 1.5361x over previous
#include <cuda_runtime.h>
#include <cuda_bf16.h>
#include <math.h>
#include <stdint.h>

#define BB   2
#define SS   2048
#define HH   2048
#define NHD  16
#define HDD  128
#define WW   512
#define BSZ  (BB*SS)          // 4096 rows

#define NEG_INF (__int_as_float(0xff800000u))

// -------- scratch (static device globals; no dynamic allocation) --------
__device__ __nv_bfloat16 g_yh [BSZ*HH];   // layernorm out, hi
__device__ __nv_bfloat16 g_yl [BSZ*HH];   // layernorm out, lo
__device__ __nv_bfloat16 g_wqh[HH*HH], g_wql[HH*HH];
__device__ __nv_bfloat16 g_wkh[HH*HH], g_wkl[HH*HH];
__device__ __nv_bfloat16 g_wvh[HH*HH], g_wvl[HH*HH];
__device__ __nv_bfloat16 g_woh[HH*HH], g_wol[HH*HH];
__device__ __nv_bfloat16 g_qh[BSZ*HH], g_ql[BSZ*HH];   // [B,NH,S,HD] bf16 hi/lo (q pre-scaled)
__device__ __nv_bfloat16 g_kh[BSZ*HH], g_kl[BSZ*HH];
__device__ __nv_bfloat16 g_vh[BSZ*HH], g_vl[BSZ*HH];
__device__ __nv_bfloat16 g_aoh[BSZ*HH];   // attn out hi  [B,S,NH,HD]
__device__ __nv_bfloat16 g_aol[BSZ*HH];   // attn out lo

// ======================= PTX helpers (compute_100-safe only) =======================
__device__ __forceinline__ uint32_t smem_u32(const void* p) {
    uint32_t a;
    asm("{ .reg .u64 t; cvta.to.shared.u64 t, %1; cvt.u32.u64 %0, t; }" : "=r"(a) : "l"(p));
    return a;
}

__device__ __forceinline__ void cp_async16(uint32_t saddr, const void* gptr) {
    asm volatile("cp.async.cg.shared.global [%0], [%1], 16;" :: "r"(saddr), "l"(gptr));
}
__device__ __forceinline__ void cp_commit() { asm volatile("cp.async.commit_group;"); }
template<int N>
__device__ __forceinline__ void cp_wait() { asm volatile("cp.async.wait_group %0;" :: "n"(N)); }

__device__ __forceinline__ void ldm_x4(uint32_t& r0, uint32_t& r1, uint32_t& r2, uint32_t& r3,
                                       uint32_t addr) {
    asm volatile("ldmatrix.sync.aligned.m8n8.x4.shared.b16 {%0,%1,%2,%3}, [%4];"
                 : "=r"(r0), "=r"(r1), "=r"(r2), "=r"(r3) : "r"(addr));
}
__device__ __forceinline__ void ldm_x4t(uint32_t& r0, uint32_t& r1, uint32_t& r2, uint32_t& r3,
                                        uint32_t addr) {
    asm volatile("ldmatrix.sync.aligned.m8n8.x4.trans.shared.b16 {%0,%1,%2,%3}, [%4];"
                 : "=r"(r0), "=r"(r1), "=r"(r2), "=r"(r3) : "r"(addr));
}

__device__ __forceinline__ void mma16816(float* c, const uint32_t* a, const uint32_t* b) {
    asm volatile("mma.sync.aligned.m16n8k16.row.col.f32.bf16.bf16.f32 "
                 "{%0,%1,%2,%3}, {%4,%5,%6,%7}, {%8,%9}, {%0,%1,%2,%3};"
                 : "+f"(c[0]), "+f"(c[1]), "+f"(c[2]), "+f"(c[3])
                 : "r"(a[0]), "r"(a[1]), "r"(a[2]), "r"(a[3]), "r"(b[0]), "r"(b[1]));
}

__device__ __forceinline__ uint32_t pack_bf16(float a, float b) {
    const __nv_bfloat16 ba = __float2bfloat16(a), bb = __float2bfloat16(b);
    return (uint32_t)(*(const uint16_t*)&ba) | ((uint32_t)(*(const uint16_t*)&bb) << 16);
}

// ======================= LayerNorm (emits bf16 hi/lo split) =======================
__device__ __forceinline__ float block_sum_2048(float s) {
    __shared__ float ws[8];
    const int lane = threadIdx.x & 31, wid = threadIdx.x >> 5;
#pragma unroll
    for (int o = 16; o > 0; o >>= 1) s += __shfl_xor_sync(0xffffffffu, s, o);
    __syncthreads();
    if (lane == 0) ws[wid] = s;
    __syncthreads();
    float t = ws[0];
#pragma unroll
    for (int i = 1; i < 8; i++) t += ws[i];
    return t;
}

__global__ void __launch_bounds__(256) ln_kernel(const float* __restrict__ x,
                                                 const float* __restrict__ gamma,
                                                 const float* __restrict__ beta,
                                                 __nv_bfloat16* __restrict__ yh,
                                                 __nv_bfloat16* __restrict__ yl)
{
    const int row = blockIdx.x;
    const int tid = threadIdx.x;
    const float* xr = x + (size_t)row * HH;
    float v[8];
#pragma unroll
    for (int i = 0; i < 8; i++) v[i] = xr[tid + i * 256];
    float s = 0.f;
#pragma unroll
    for (int i = 0; i < 8; i++) s += v[i];
    const float mu = block_sum_2048(s) * (1.0f / HH);
    float sq = 0.f;
#pragma unroll
    for (int i = 0; i < 8; i++) { float d = v[i] - mu; sq += d * d; }
    const float var = block_sum_2048(sq) * (1.0f / HH);
    const float rs = rsqrtf(var + 1e-6f);
#pragma unroll
    for (int i = 0; i < 8; i++) {
        const int c = tid + i * 256;
        const float val = (v[i] - mu) * rs * gamma[c] + beta[c];
        const __nv_bfloat16 h = __float2bfloat16(val);
        yh[(size_t)row * HH + c] = h;
        yl[(size_t)row * HH + c] = __float2bfloat16(val - __bfloat162float(h));
    }
}

// ======================= Weight transpose + bf16 split: W[K][N] -> Wh/Wl[N][K] =======================
__global__ void __launch_bounds__(256) wsplit_kernel(const float* __restrict__ W,
                                                     __nv_bfloat16* __restrict__ Wh,
                                                     __nv_bfloat16* __restrict__ Wl)
{
    __shared__ float t[32][33];
    const int tx = threadIdx.x & 31, ty = threadIdx.x >> 5;
    const int n = blockIdx.x * 32 + tx;
#pragma unroll
    for (int i = 0; i < 4; i++) {
        const int k = blockIdx.y * 32 + ty + i * 8;
        t[ty + i * 8][tx] = W[(size_t)k * HH + n];
    }
    __syncthreads();
#pragma unroll
    for (int i = 0; i < 4; i++) {
        const int nn = blockIdx.x * 32 + ty + i * 8;
        const int kk = blockIdx.y * 32 + tx;
        const float v = t[tx][ty + i * 8];
        const __nv_bfloat16 h = __float2bfloat16(v);
        Wh[(size_t)nn * HH + kk] = h;
        Wl[(size_t)nn * HH + kk] = __float2bfloat16(v - __bfloat162float(h));
    }
}

// ======================= mma.sync GEMM: C[4096,2048] = alpha*(A @ B^T + bias) =======================
#define GP_ROWB   80
#define GP_MAT    (128 * GP_ROWB)
#define GP_STAGE  (4 * GP_MAT)          // 40960 B
#define GP_SMEM   (2 * GP_STAGE)        // 81920 B

__device__ __forceinline__ void gemm_load_chunk(
    uint32_t sstage, int k0, int m0, int n0, int tid,
    const __nv_bfloat16* __restrict__ Ah, const __nv_bfloat16* __restrict__ Al,
    const __nv_bfloat16* __restrict__ Bh, const __nv_bfloat16* __restrict__ Bl)
{
#pragma unroll
    for (int mat = 0; mat < 4; ++mat) {
        const __nv_bfloat16* src = (mat == 0) ? Ah : (mat == 1) ? Al : (mat == 2) ? Bh : Bl;
        const int gbase = (mat < 2) ? m0 : n0;
        const uint32_t sb = sstage + mat * GP_MAT;
#pragma unroll
        for (int j = 0; j < 2; ++j) {
            const int idx = tid + j * 256;
            const int row = idx >> 2, c16 = idx & 3;
            cp_async16(sb + row * GP_ROWB + c16 * 16,
                       src + (size_t)(gbase + row) * HH + k0 + c16 * 8);
        }
    }
    cp_commit();
}

// OUT_MODE 0: fp32 row-major [M,N] -> C.   OUT_MODE 1: bf16 hi/lo QKV scatter [B,NH,S,HD].
template<int OUT_MODE>
__global__ void __launch_bounds__(256, 2) gemm_mma(
    const __nv_bfloat16* __restrict__ Ah, const __nv_bfloat16* __restrict__ Al,
    const __nv_bfloat16* __restrict__ Bh, const __nv_bfloat16* __restrict__ Bl,
    const float* __restrict__ bias, float alpha, float* __restrict__ C,
    __nv_bfloat16* __restrict__ Ch, __nv_bfloat16* __restrict__ Cl)
{
    extern __shared__ char sm8[];
    const uint32_t sbase = smem_u32(sm8);
    const int tid = threadIdx.x;
    const int wid = tid >> 5, lane = tid & 31;
    const int m0 = blockIdx.y * 128, n0 = blockIdx.x * 128;
    const int m_w = (wid >> 1) * 32, n_w = (wid & 1) * 64;

    float acc[2][8][4];
#pragma unroll
    for (int i = 0; i < 2; i++)
#pragma unroll
        for (int j = 0; j < 8; j++)
#pragma unroll
            for (int q = 0; q < 4; q++) acc[i][j][q] = 0.f;

    gemm_load_chunk(sbase, 0, m0, n0, tid, Ah, Al, Bh, Bl);

    const int arow = lane & 15, khalf = (lane >> 4) * 8;

    for (int kc = 0; kc < HH / 32; ++kc) {
        if (kc + 1 < HH / 32) {
            gemm_load_chunk(sbase + ((kc + 1) & 1) * GP_STAGE, (kc + 1) * 32, m0, n0, tid,
                            Ah, Al, Bh, Bl);
            cp_wait<1>();
        } else {
            cp_wait<0>();
        }
        __syncthreads();

        const uint32_t st = sbase + (kc & 1) * GP_STAGE;
#pragma unroll
        for (int ks = 0; ks < 2; ++ks) {
            const int kb = (ks * 16 + khalf) * 2;
            uint32_t ah[2][4], al[2][4];
#pragma unroll
            for (int mi = 0; mi < 2; ++mi) {
                const uint32_t roff = (m_w + mi * 16 + arow) * GP_ROWB + kb;
                ldm_x4(ah[mi][0], ah[mi][1], ah[mi][2], ah[mi][3], st + 0 * GP_MAT + roff);
                ldm_x4(al[mi][0], al[mi][1], al[mi][2], al[mi][3], st + 1 * GP_MAT + roff);
            }
            uint32_t bh[8][2], bl[8][2];
#pragma unroll
            for (int nf = 0; nf < 4; ++nf) {
                const uint32_t roff = (n_w + nf * 16 + arow) * GP_ROWB + kb;
                uint32_t r0, r1, r2, r3;
                ldm_x4(r0, r1, r2, r3, st + 2 * GP_MAT + roff);
                bh[2 * nf][0] = r0; bh[2 * nf][1] = r2;
                bh[2 * nf + 1][0] = r1; bh[2 * nf + 1][1] = r3;
                ldm_x4(r0, r1, r2, r3, st + 3 * GP_MAT + roff);
                bl[2 * nf][0] = r0; bl[2 * nf][1] = r2;
                bl[2 * nf + 1][0] = r1; bl[2 * nf + 1][1] = r3;
            }
#pragma unroll
            for (int mi = 0; mi < 2; ++mi)
#pragma unroll
                for (int nj = 0; nj < 8; ++nj) {
                    mma16816(acc[mi][nj], ah[mi], bh[nj]);
                    mma16816(acc[mi][nj], ah[mi], bl[nj]);
                    mma16816(acc[mi][nj], al[mi], bh[nj]);
                }
        }
        __syncthreads();
    }

    const int g = lane >> 2, qn = (lane & 3) * 2;
#pragma unroll
    for (int mi = 0; mi < 2; ++mi) {
#pragma unroll
        for (int h = 0; h < 2; ++h) {
            const int row = m0 + m_w + mi * 16 + g + h * 8;
            if (OUT_MODE == 0) {
                float* dst = C + (size_t)row * HH + n0;
#pragma unroll
                for (int nf = 0; nf < 8; ++nf) {
                    const int col = n_w + nf * 8 + qn;
                    float2 ov;
                    ov.x = alpha * (acc[mi][nf][h * 2 + 0] + bias[n0 + col]);
                    ov.y = alpha * (acc[mi][nf][h * 2 + 1] + bias[n0 + col + 1]);
                    *(float2*)(dst + col) = ov;
                }
            } else {
                const int b_ = row >> 11, s_ = row & (SS - 1);
                const size_t base = ((size_t)((b_ * NHD + blockIdx.x) * SS + s_)) * HDD;
#pragma unroll
                for (int nf = 0; nf < 8; ++nf) {
                    const int col = n_w + nf * 8 + qn;
                    const float v0 = alpha * (acc[mi][nf][h * 2 + 0] + bias[n0 + col]);
                    const float v1 = alpha * (acc[mi][nf][h * 2 + 1] + bias[n0 + col + 1]);
                    const __nv_bfloat16 h0 = __float2bfloat16(v0);
                    const __nv_bfloat16 h1 = __float2bfloat16(v1);
                    const float r0f = v0 - __bfloat162float(h0);
                    const float r1f = v1 - __bfloat162float(h1);
                    *(uint32_t*)(Ch + base + col) = pack_bf16(v0, v1);
                    *(uint32_t*)(Cl + base + col) = pack_bf16(r0f, r1f);
                }
            }
        }
    }
}

// ======================= mma.sync flash attention (complement-of-window mask) =======================
// masked (excluded) iff 0 <= qi - kj < W.  Fully-masked 128-tiles: (i0>>7) - jt in {1,2,3}.
#define AT_STRIDE 272                    // bytes per smem row (128 bf16 + 16B pad)
#define AT_MAT    (128 * AT_STRIDE)      // 34816
#define AT_SMEM   (6 * AT_MAT)           // 208896

__device__ __forceinline__ void attn_load(uint32_t dst, const __nv_bfloat16* __restrict__ g,
                                          int row0, int tid)
{
    const __nv_bfloat16* gp = g + (size_t)row0 * HDD;
#pragma unroll
    for (int i = 0; i < 8; i++) {
        const int idx = tid + i * 256;
        const int r = idx >> 4, c = idx & 15;
        cp_async16(dst + r * AT_STRIDE + c * 16, gp + r * HDD + c * 8);
    }
}

__global__ void __launch_bounds__(256) attn_mma()
{
    extern __shared__ char smx[];
    const uint32_t sb = smem_u32(smx);
    const uint32_t Qh = sb,              Ql = sb + 1 * AT_MAT;
    const uint32_t Kh = sb + 2 * AT_MAT, Kl = sb + 3 * AT_MAT;
    const uint32_t Vh = sb + 4 * AT_MAT, Vl = sb + 5 * AT_MAT;

    const int i0 = blockIdx.x * 128;
    const int head = blockIdx.y;
    const int b = blockIdx.z;
    const size_t hb = (size_t)(b * NHD + head) * SS * HDD;
    const __nv_bfloat16 *qhB = g_qh + hb, *qlB = g_ql + hb;
    const __nv_bfloat16 *khB = g_kh + hb, *klB = g_kl + hb;
    const __nv_bfloat16 *vhB = g_vh + hb, *vlB = g_vl + hb;

    const int tid = threadIdx.x, wid = tid >> 5, lane = tid & 31;
    const int arow = lane & 15, khalf16 = (lane >> 4) * 16;   // byte offset half
    const int g = lane >> 2, q = lane & 3;
    const int row0 = i0 + wid * 16 + g;            // second row = row0 + 8

    // list of non-fully-masked key tiles
    int tiles[16]; int nt = 0;
    const int bi = i0 >> 7;
#pragma unroll
    for (int jt = 0; jt < 16; jt++) {
        const int d = bi - jt;
        if (d != 1 && d != 2 && d != 3) tiles[nt++] = jt;
    }

    // prologue loads: Q + K(t0) in group 0; V(t0) in group 1
    attn_load(Qh, qhB, i0, tid);
    attn_load(Ql, qlB, i0, tid);
    attn_load(Kh, khB, tiles[0] * 128, tid);
    attn_load(Kl, klB, tiles[0] * 128, tid);
    cp_commit();
    attn_load(Vh, vhB, tiles[0] * 128, tid);
    attn_load(Vl, vlB, tiles[0] * 128, tid);
    cp_commit();

    float o[16][4];
#pragma unroll
    for (int t = 0; t < 16; t++)
#pragma unroll
        for (int c = 0; c < 4; c++) o[t][c] = 0.f;
    float m0 = NEG_INF, m1 = NEG_INF, l0 = 0.f, l1 = 0.f;

    for (int ti = 0; ti < nt; ti++) {
        const int j0 = tiles[ti] * 128;

        cp_wait<1>();          // K(ti) (+Q) ready; V(ti) may still be in flight
        __syncthreads();

        // ---- S = Q K^T (3-term split) ----
        float s[16][4];
#pragma unroll
        for (int t = 0; t < 16; t++)
#pragma unroll
            for (int c = 0; c < 4; c++) s[t][c] = 0.f;

#pragma unroll
        for (int ks = 0; ks < 8; ks++) {
            const uint32_t kb = ks * 32 + khalf16;
            uint32_t qh4[4], ql4[4];
            const uint32_t aoff = (wid * 16 + arow) * AT_STRIDE + kb;
            ldm_x4(qh4[0], qh4[1], qh4[2], qh4[3], Qh + aoff);
            ldm_x4(ql4[0], ql4[1], ql4[2], ql4[3], Ql + aoff);
#pragma unroll
            for (int nf = 0; nf < 8; nf++) {
                const uint32_t roff = (nf * 16 + arow) * AT_STRIDE + kb;
                uint32_t r0, r1, r2, r3, u0, u1, u2, u3;
                ldm_x4(r0, r1, r2, r3, Kh + roff);
                ldm_x4(u0, u1, u2, u3, Kl + roff);
                uint32_t bh0[2] = {r0, r2}, bh1[2] = {r1, r3};
                uint32_t bl0[2] = {u0, u2}, bl1[2] = {u1, u3};
                mma16816(s[2 * nf], qh4, bh0);
                mma16816(s[2 * nf], qh4, bl0);
                mma16816(s[2 * nf], ql4, bh0);
                mma16816(s[2 * nf + 1], qh4, bh1);
                mma16816(s[2 * nf + 1], qh4, bl1);
                mma16816(s[2 * nf + 1], ql4, bh1);
            }
        }

        // ---- mask + online softmax (warp-local; rows row0, row0+8) ----
#pragma unroll
        for (int t = 0; t < 16; t++) {
            const int kj = j0 + 8 * t + 2 * q;
#pragma unroll
            for (int c = 0; c < 4; c++) {
                const int qi = (c < 2) ? row0 : row0 + 8;
                const int dl = qi - (kj + (c & 1));
                if (dl >= 0 && dl < WW) s[t][c] = NEG_INF;
            }
        }
        float rm0 = NEG_INF, rm1 = NEG_INF;
#pragma unroll
        for (int t = 0; t < 16; t++) {
            rm0 = fmaxf(rm0, fmaxf(s[t][0], s[t][1]));
            rm1 = fmaxf(rm1, fmaxf(s[t][2], s[t][3]));
        }
        rm0 = fmaxf(rm0, __shfl_xor_sync(0xffffffffu, rm0, 1));
        rm0 = fmaxf(rm0, __shfl_xor_sync(0xffffffffu, rm0, 2));
        rm1 = fmaxf(rm1, __shfl_xor_sync(0xffffffffu, rm1, 1));
        rm1 = fmaxf(rm1, __shfl_xor_sync(0xffffffffu, rm1, 2));
        const float mn0 = fmaxf(m0, rm0), mn1 = fmaxf(m1, rm1);
        const float c0 = (m0 == mn0) ? 1.f : __expf(m0 - mn0);
        const float c1 = (m1 == mn1) ? 1.f : __expf(m1 - mn1);
        float sum0 = 0.f, sum1 = 0.f;
#pragma unroll
        for (int t = 0; t < 16; t++) {
#pragma unroll
            for (int c = 0; c < 4; c++) {
                const float sv = s[t][c];
                const float mn = (c < 2) ? mn0 : mn1;
                const float p = (sv == NEG_INF) ? 0.f : __expf(sv - mn);
                s[t][c] = p;
                if (c < 2) sum0 += p; else sum1 += p;
            }
        }
        sum0 += __shfl_xor_sync(0xffffffffu, sum0, 1);
        sum0 += __shfl_xor_sync(0xffffffffu, sum0, 2);
        sum1 += __shfl_xor_sync(0xffffffffu, sum1, 1);
        sum1 += __shfl_xor_sync(0xffffffffu, sum1, 2);
        l0 = l0 * c0 + sum0; m0 = mn0;
        l1 = l1 * c1 + sum1; m1 = mn1;
#pragma unroll
        for (int t = 0; t < 16; t++) {
            o[t][0] *= c0; o[t][1] *= c0; o[t][2] *= c1; o[t][3] *= c1;
        }

        __syncthreads();       // all warps done reading K
        if (ti + 1 < nt) {
            const int jn = tiles[ti + 1] * 128;
            attn_load(Kh, khB, jn, tid);
            attn_load(Kl, klB, jn, tid);
        }
        cp_commit();           // K(ti+1) group (possibly empty)

        cp_wait<1>();          // V(ti) ready (pending: K(ti+1))
        __syncthreads();

        // ---- O += P V (3-term split; V fragments via ldmatrix.trans) ----
#pragma unroll
        for (int u = 0; u < 8; u++) {
            uint32_t ph[4], pl[4];
            {
                const float p00 = s[2 * u][0],     p01 = s[2 * u][1];
                const float p02 = s[2 * u][2],     p03 = s[2 * u][3];
                const float p10 = s[2 * u + 1][0], p11 = s[2 * u + 1][1];
                const float p12 = s[2 * u + 1][2], p13 = s[2 * u + 1][3];
                ph[0] = pack_bf16(p00, p01);
                ph[1] = pack_bf16(p02, p03);
                ph[2] = pack_bf16(p10, p11);
                ph[3] = pack_bf16(p12, p13);
                pl[0] = pack_bf16(p00 - __bfloat162float(__float2bfloat16(p00)),
                                  p01 - __bfloat162float(__float2bfloat16(p01)));
                pl[1] = pack_bf16(p02 - __bfloat162float(__float2bfloat16(p02)),
                                  p03 - __bfloat162float(__float2bfloat16(p03)));
                pl[2] = pack_bf16(p10 - __bfloat162float(__float2bfloat16(p10)),
                                  p11 - __bfloat162float(__float2bfloat16(p11)));
                pl[3] = pack_bf16(p12 - __bfloat162float(__float2bfloat16(p12)),
                                  p13 - __bfloat162float(__float2bfloat16(p13)));
            }
#pragma unroll
            for (int dp = 0; dp < 8; dp++) {
                const uint32_t roff = (u * 16 + arow) * AT_STRIDE + dp * 32 + khalf16;
                uint32_t r0, r1, r2, r3, u0, u1, u2, u3;
                ldm_x4t(r0, r1, r2, r3, Vh + roff);
                ldm_x4t(u0, u1, u2, u3, Vl + roff);
                uint32_t bvh0[2] = {r0, r1}, bvh1[2] = {r2, r3};
                uint32_t bvl0[2] = {u0, u1}, bvl1[2] = {u2, u3};
                mma16816(o[2 * dp], ph, bvh0);
                mma16816(o[2 * dp], ph, bvl0);
                mma16816(o[2 * dp], pl, bvh0);
                mma16816(o[2 * dp + 1], ph, bvh1);
                mma16816(o[2 * dp + 1], ph, bvl1);
                mma16816(o[2 * dp + 1], pl, bvh1);
            }
        }

        __syncthreads();       // all warps done reading V
        if (ti + 1 < nt) {
            const int jn = tiles[ti + 1] * 128;
            attn_load(Vh, vhB, jn, tid);
            attn_load(Vl, vlB, jn, tid);
        }
        cp_commit();           // V(ti+1) group (possibly empty)
    }

    // ---- epilogue: normalize, split hi/lo, write [B,S,NH,HD] ----
    const float inv0 = 1.f / l0, inv1 = 1.f / l1;
    const size_t base0 = ((size_t)(b * SS + row0) * NHD + head) * HDD;
    const size_t base1 = base0 + (size_t)8 * NHD * HDD;
#pragma unroll
    for (int t = 0; t < 16; t++) {
        const int d = 8 * t + 2 * q;
        const float f0 = o[t][0] * inv0, f1 = o[t][1] * inv0;
        const float f2 = o[t][2] * inv1, f3 = o[t][3] * inv1;
        *(uint32_t*)(g_aoh + base0 + d) = pack_bf16(f0, f1);
        *(uint32_t*)(g_aol + base0 + d) =
            pack_bf16(f0 - __bfloat162float(__float2bfloat16(f0)),
                      f1 - __bfloat162float(__float2bfloat16(f1)));
        *(uint32_t*)(g_aoh + base1 + d) = pack_bf16(f2, f3);
        *(uint32_t*)(g_aol + base1 + d) =
            pack_bf16(f2 - __bfloat162float(__float2bfloat16(f2)),
                      f3 - __bfloat162float(__float2bfloat16(f3)));
    }
}

// ======================= launch =======================
extern "C" void kernel_launch(void* const* d_in, const int* in_sizes, int n_in,
                              void* d_out, int out_size)
{
    (void)in_sizes; (void)n_in; (void)out_size;
    const float* x   = (const float*)d_in[0];
    const float* lns = (const float*)d_in[1];
    const float* lnb = (const float*)d_in[2];
    const float* wq  = (const float*)d_in[3];
    const float* bq  = (const float*)d_in[4];
    const float* wk  = (const float*)d_in[5];
    const float* bk  = (const float*)d_in[6];
    const float* wv  = (const float*)d_in[7];
    const float* bv  = (const float*)d_in[8];
    const float* wo  = (const float*)d_in[9];
    const float* bo  = (const float*)d_in[10];
    float* out = (float*)d_out;

    __nv_bfloat16 *pyh, *pyl, *pwqh, *pwql, *pwkh, *pwkl, *pwvh, *pwvl, *pwoh, *pwol;
    __nv_bfloat16 *pqh, *pql, *pkh, *pkl, *pvh, *pvl, *paoh, *paol;
    cudaGetSymbolAddress((void**)&pyh, g_yh);   cudaGetSymbolAddress((void**)&pyl, g_yl);
    cudaGetSymbolAddress((void**)&pwqh, g_wqh); cudaGetSymbolAddress((void**)&pwql, g_wql);
    cudaGetSymbolAddress((void**)&pwkh, g_wkh); cudaGetSymbolAddress((void**)&pwkl, g_wkl);
    cudaGetSymbolAddress((void**)&pwvh, g_wvh); cudaGetSymbolAddress((void**)&pwvl, g_wvl);
    cudaGetSymbolAddress((void**)&pwoh, g_woh); cudaGetSymbolAddress((void**)&pwol, g_wol);
    cudaGetSymbolAddress((void**)&pqh, g_qh);   cudaGetSymbolAddress((void**)&pql, g_ql);
    cudaGetSymbolAddress((void**)&pkh, g_kh);   cudaGetSymbolAddress((void**)&pkl, g_kl);
    cudaGetSymbolAddress((void**)&pvh, g_vh);   cudaGetSymbolAddress((void**)&pvl, g_vl);
    cudaGetSymbolAddress((void**)&paoh, g_aoh); cudaGetSymbolAddress((void**)&paol, g_aol);

    ln_kernel<<<BSZ, 256>>>(x, lns, lnb, pyh, pyl);

    dim3 wg(HH / 32, HH / 32);
    wsplit_kernel<<<wg, 256>>>(wq, pwqh, pwql);
    wsplit_kernel<<<wg, 256>>>(wk, pwkh, pwkl);
    wsplit_kernel<<<wg, 256>>>(wv, pwvh, pwvl);
    wsplit_kernel<<<wg, 256>>>(wo, pwoh, pwol);

    cudaFuncSetAttribute(gemm_mma<0>, cudaFuncAttributeMaxDynamicSharedMemorySize, GP_SMEM);
    cudaFuncSetAttribute(gemm_mma<1>, cudaFuncAttributeMaxDynamicSharedMemorySize, GP_SMEM);

    dim3 gg(HH / 128, BSZ / 128);   // (16, 32)
    const float qscale = 0.08838834764831845f;   // 1/sqrt(128)
    gemm_mma<1><<<gg, 256, GP_SMEM>>>(pyh, pyl, pwqh, pwql, bq, qscale, nullptr, pqh, pql);
    gemm_mma<1><<<gg, 256, GP_SMEM>>>(pyh, pyl, pwkh, pwkl, bk, 1.f, nullptr, pkh, pkl);
    gemm_mma<1><<<gg, 256, GP_SMEM>>>(pyh, pyl, pwvh, pwvl, bv, 1.f, nullptr, pvh, pvl);

    cudaFuncSetAttribute(attn_mma, cudaFuncAttributeMaxDynamicSharedMemorySize, AT_SMEM);
    attn_mma<<<dim3(SS / 128, NHD, BB), 256, AT_SMEM>>>();

    gemm_mma<0><<<gg, 256, GP_SMEM>>>(paoh, paol, pwoh, pwol, bo, 1.f, out, nullptr, nullptr);
}

// round 5
// speedup vs baseline: 2.1625x; 1.0489x over previous
#include <cuda_runtime.h>
#include <cuda_bf16.h>
#include <math.h>
#include <stdint.h>

#define BB   2
#define SS   2048
#define HH   2048
#define NHD  16
#define HDD  128
#define WW   512
#define BSZ  (BB*SS)          // 4096 rows

#define NEG_INF (__int_as_float(0xff800000u))

// -------- scratch (static device globals; no dynamic allocation) --------
__device__ __nv_bfloat16 g_yh [BSZ*HH];   // layernorm out, hi
__device__ __nv_bfloat16 g_yl [BSZ*HH];   // layernorm out, lo
__device__ __nv_bfloat16 g_wqh[HH*HH], g_wql[HH*HH];
__device__ __nv_bfloat16 g_wkh[HH*HH], g_wkl[HH*HH];
__device__ __nv_bfloat16 g_wvh[HH*HH], g_wvl[HH*HH];
__device__ __nv_bfloat16 g_woh[HH*HH], g_wol[HH*HH];
__device__ __nv_bfloat16 g_qh[BSZ*HH], g_ql[BSZ*HH];   // [B,NH,S,HD] bf16 hi/lo (q pre-scaled)
__device__ __nv_bfloat16 g_kh[BSZ*HH], g_kl[BSZ*HH];
__device__ __nv_bfloat16 g_vh[BSZ*HH], g_vl[BSZ*HH];
__device__ __nv_bfloat16 g_aoh[BSZ*HH];   // attn out hi  [B,S,NH,HD]
__device__ __nv_bfloat16 g_aol[BSZ*HH];   // attn out lo

// ======================= PTX helpers (compute_100-safe only) =======================
__device__ __forceinline__ uint32_t smem_u32(const void* p) {
    uint32_t a;
    asm("{ .reg .u64 t; cvta.to.shared.u64 t, %1; cvt.u32.u64 %0, t; }" : "=r"(a) : "l"(p));
    return a;
}

__device__ __forceinline__ void cp_async16(uint32_t saddr, const void* gptr) {
    asm volatile("cp.async.cg.shared.global [%0], [%1], 16;" :: "r"(saddr), "l"(gptr));
}
__device__ __forceinline__ void cp_commit() { asm volatile("cp.async.commit_group;"); }
template<int N>
__device__ __forceinline__ void cp_wait() { asm volatile("cp.async.wait_group %0;" :: "n"(N)); }

__device__ __forceinline__ void ldm_x4(uint32_t& r0, uint32_t& r1, uint32_t& r2, uint32_t& r3,
                                       uint32_t addr) {
    asm volatile("ldmatrix.sync.aligned.m8n8.x4.shared.b16 {%0,%1,%2,%3}, [%4];"
                 : "=r"(r0), "=r"(r1), "=r"(r2), "=r"(r3) : "r"(addr));
}
__device__ __forceinline__ void ldm_x4t(uint32_t& r0, uint32_t& r1, uint32_t& r2, uint32_t& r3,
                                        uint32_t addr) {
    asm volatile("ldmatrix.sync.aligned.m8n8.x4.trans.shared.b16 {%0,%1,%2,%3}, [%4];"
                 : "=r"(r0), "=r"(r1), "=r"(r2), "=r"(r3) : "r"(addr));
}

__device__ __forceinline__ void mma16816(float* c, const uint32_t* a, const uint32_t* b) {
    asm volatile("mma.sync.aligned.m16n8k16.row.col.f32.bf16.bf16.f32 "
                 "{%0,%1,%2,%3}, {%4,%5,%6,%7}, {%8,%9}, {%0,%1,%2,%3};"
                 : "+f"(c[0]), "+f"(c[1]), "+f"(c[2]), "+f"(c[3])
                 : "r"(a[0]), "r"(a[1]), "r"(a[2]), "r"(a[3]), "r"(b[0]), "r"(b[1]));
}

__device__ __forceinline__ uint32_t pack_bf16(float a, float b) {
    const __nv_bfloat16 ba = __float2bfloat16(a), bb = __float2bfloat16(b);
    return (uint32_t)(*(const uint16_t*)&ba) | ((uint32_t)(*(const uint16_t*)&bb) << 16);
}

// ======================= LayerNorm (emits bf16 hi/lo split) =======================
__device__ __forceinline__ float block_sum_2048(float s) {
    __shared__ float ws[8];
    const int lane = threadIdx.x & 31, wid = threadIdx.x >> 5;
#pragma unroll
    for (int o = 16; o > 0; o >>= 1) s += __shfl_xor_sync(0xffffffffu, s, o);
    __syncthreads();
    if (lane == 0) ws[wid] = s;
    __syncthreads();
    float t = ws[0];
#pragma unroll
    for (int i = 1; i < 8; i++) t += ws[i];
    return t;
}

__global__ void __launch_bounds__(256) ln_kernel(const float* __restrict__ x,
                                                 const float* __restrict__ gamma,
                                                 const float* __restrict__ beta,
                                                 __nv_bfloat16* __restrict__ yh,
                                                 __nv_bfloat16* __restrict__ yl)
{
    const int row = blockIdx.x;
    const int tid = threadIdx.x;
    const float* xr = x + (size_t)row * HH;
    float v[8];
#pragma unroll
    for (int i = 0; i < 8; i++) v[i] = xr[tid + i * 256];
    float s = 0.f;
#pragma unroll
    for (int i = 0; i < 8; i++) s += v[i];
    const float mu = block_sum_2048(s) * (1.0f / HH);
    float sq = 0.f;
#pragma unroll
    for (int i = 0; i < 8; i++) { float d = v[i] - mu; sq += d * d; }
    const float var = block_sum_2048(sq) * (1.0f / HH);
    const float rs = rsqrtf(var + 1e-6f);
#pragma unroll
    for (int i = 0; i < 8; i++) {
        const int c = tid + i * 256;
        const float val = (v[i] - mu) * rs * gamma[c] + beta[c];
        const __nv_bfloat16 h = __float2bfloat16(val);
        yh[(size_t)row * HH + c] = h;
        yl[(size_t)row * HH + c] = __float2bfloat16(val - __bfloat162float(h));
    }
}

// ============ Merged weight transpose + bf16 split: 4 weights in one launch ============
__global__ void __launch_bounds__(256) wsplit_all(
    const float* __restrict__ w0, const float* __restrict__ w1,
    const float* __restrict__ w2, const float* __restrict__ w3,
    __nv_bfloat16* __restrict__ h0, __nv_bfloat16* __restrict__ l0,
    __nv_bfloat16* __restrict__ h1, __nv_bfloat16* __restrict__ l1,
    __nv_bfloat16* __restrict__ h2, __nv_bfloat16* __restrict__ l2,
    __nv_bfloat16* __restrict__ h3, __nv_bfloat16* __restrict__ l3)
{
    const int z = blockIdx.z;
    const float* W = (z == 0) ? w0 : (z == 1) ? w1 : (z == 2) ? w2 : w3;
    __nv_bfloat16* Wh = (z == 0) ? h0 : (z == 1) ? h1 : (z == 2) ? h2 : h3;
    __nv_bfloat16* Wl = (z == 0) ? l0 : (z == 1) ? l1 : (z == 2) ? l2 : l3;

    __shared__ float t[32][33];
    const int tx = threadIdx.x & 31, ty = threadIdx.x >> 5;
    const int n = blockIdx.x * 32 + tx;
#pragma unroll
    for (int i = 0; i < 4; i++) {
        const int k = blockIdx.y * 32 + ty + i * 8;
        t[ty + i * 8][tx] = W[(size_t)k * HH + n];
    }
    __syncthreads();
#pragma unroll
    for (int i = 0; i < 4; i++) {
        const int nn = blockIdx.x * 32 + ty + i * 8;
        const int kk = blockIdx.y * 32 + tx;
        const float v = t[tx][ty + i * 8];
        const __nv_bfloat16 h = __float2bfloat16(v);
        Wh[(size_t)nn * HH + kk] = h;
        Wl[(size_t)nn * HH + kk] = __float2bfloat16(v - __bfloat162float(h));
    }
}

// ======================= mma.sync GEMM core =======================
#define GP_ROWB   80
#define GP_MAT    (128 * GP_ROWB)
#define GP_STAGE  (4 * GP_MAT)          // 40960 B
#define GP_SMEM   (2 * GP_STAGE)        // 81920 B

__device__ __forceinline__ void gemm_load_chunk(
    uint32_t sstage, int k0, int m0, int n0, int tid,
    const __nv_bfloat16* __restrict__ Ah, const __nv_bfloat16* __restrict__ Al,
    const __nv_bfloat16* __restrict__ Bh, const __nv_bfloat16* __restrict__ Bl)
{
#pragma unroll
    for (int mat = 0; mat < 4; ++mat) {
        const __nv_bfloat16* src = (mat == 0) ? Ah : (mat == 1) ? Al : (mat == 2) ? Bh : Bl;
        const int gbase = (mat < 2) ? m0 : n0;
        const uint32_t sb = sstage + mat * GP_MAT;
#pragma unroll
        for (int j = 0; j < 2; ++j) {
            const int idx = tid + j * 256;
            const int row = idx >> 2, c16 = idx & 3;
            cp_async16(sb + row * GP_ROWB + c16 * 16,
                       src + (size_t)(gbase + row) * HH + k0 + c16 * 8);
        }
    }
    cp_commit();
}

// mainloop producing acc[2][8][4] for a 128x128 tile
__device__ __forceinline__ void gemm_core(
    uint32_t sbase, int m0, int n0, int tid,
    const __nv_bfloat16* __restrict__ Ah, const __nv_bfloat16* __restrict__ Al,
    const __nv_bfloat16* __restrict__ Bh, const __nv_bfloat16* __restrict__ Bl,
    float acc[2][8][4])
{
    const int wid = tid >> 5, lane = tid & 31;
    const int m_w = (wid >> 1) * 32, n_w = (wid & 1) * 64;
    const int arow = lane & 15, khalf = (lane >> 4) * 8;

    gemm_load_chunk(sbase, 0, m0, n0, tid, Ah, Al, Bh, Bl);

    for (int kc = 0; kc < HH / 32; ++kc) {
        if (kc + 1 < HH / 32) {
            gemm_load_chunk(sbase + ((kc + 1) & 1) * GP_STAGE, (kc + 1) * 32, m0, n0, tid,
                            Ah, Al, Bh, Bl);
            cp_wait<1>();
        } else {
            cp_wait<0>();
        }
        __syncthreads();

        const uint32_t st = sbase + (kc & 1) * GP_STAGE;
#pragma unroll
        for (int ks = 0; ks < 2; ++ks) {
            const int kb = (ks * 16 + khalf) * 2;
            uint32_t ah[2][4], al[2][4];
#pragma unroll
            for (int mi = 0; mi < 2; ++mi) {
                const uint32_t roff = (m_w + mi * 16 + arow) * GP_ROWB + kb;
                ldm_x4(ah[mi][0], ah[mi][1], ah[mi][2], ah[mi][3], st + 0 * GP_MAT + roff);
                ldm_x4(al[mi][0], al[mi][1], al[mi][2], al[mi][3], st + 1 * GP_MAT + roff);
            }
            uint32_t bh[8][2], bl[8][2];
#pragma unroll
            for (int nf = 0; nf < 4; ++nf) {
                const uint32_t roff = (n_w + nf * 16 + arow) * GP_ROWB + kb;
                uint32_t r0, r1, r2, r3;
                ldm_x4(r0, r1, r2, r3, st + 2 * GP_MAT + roff);
                bh[2 * nf][0] = r0; bh[2 * nf][1] = r2;
                bh[2 * nf + 1][0] = r1; bh[2 * nf + 1][1] = r3;
                ldm_x4(r0, r1, r2, r3, st + 3 * GP_MAT + roff);
                bl[2 * nf][0] = r0; bl[2 * nf][1] = r2;
                bl[2 * nf + 1][0] = r1; bl[2 * nf + 1][1] = r3;
            }
#pragma unroll
            for (int mi = 0; mi < 2; ++mi)
#pragma unroll
                for (int nj = 0; nj < 8; ++nj) {
                    mma16816(acc[mi][nj], ah[mi], bh[nj]);
                    mma16816(acc[mi][nj], ah[mi], bl[nj]);
                    mma16816(acc[mi][nj], al[mi], bh[nj]);
                }
        }
        __syncthreads();
    }
}

// ---- merged QKV GEMM: z selects weight; output scatter bf16 hi/lo [B,NH,S,HD] ----
__global__ void __launch_bounds__(256, 2) gemm_qkv(
    const __nv_bfloat16* __restrict__ Ah, const __nv_bfloat16* __restrict__ Al,
    const __nv_bfloat16* __restrict__ Bh0, const __nv_bfloat16* __restrict__ Bl0,
    const __nv_bfloat16* __restrict__ Bh1, const __nv_bfloat16* __restrict__ Bl1,
    const __nv_bfloat16* __restrict__ Bh2, const __nv_bfloat16* __restrict__ Bl2,
    const float* __restrict__ bias0, const float* __restrict__ bias1,
    const float* __restrict__ bias2,
    __nv_bfloat16* __restrict__ Ch0, __nv_bfloat16* __restrict__ Cl0,
    __nv_bfloat16* __restrict__ Ch1, __nv_bfloat16* __restrict__ Cl1,
    __nv_bfloat16* __restrict__ Ch2, __nv_bfloat16* __restrict__ Cl2)
{
    extern __shared__ char sm8[];
    const uint32_t sbase = smem_u32(sm8);
    const int tid = threadIdx.x;
    const int z = blockIdx.z;
    const __nv_bfloat16* Bh = (z == 0) ? Bh0 : (z == 1) ? Bh1 : Bh2;
    const __nv_bfloat16* Bl = (z == 0) ? Bl0 : (z == 1) ? Bl1 : Bl2;
    const float* bias = (z == 0) ? bias0 : (z == 1) ? bias1 : bias2;
    __nv_bfloat16* Ch = (z == 0) ? Ch0 : (z == 1) ? Ch1 : Ch2;
    __nv_bfloat16* Cl = (z == 0) ? Cl0 : (z == 1) ? Cl1 : Cl2;
    const float alpha = (z == 0) ? 0.08838834764831845f : 1.f;

    const int m0 = blockIdx.y * 128, n0 = blockIdx.x * 128;

    float acc[2][8][4];
#pragma unroll
    for (int i = 0; i < 2; i++)
#pragma unroll
        for (int j = 0; j < 8; j++)
#pragma unroll
            for (int q = 0; q < 4; q++) acc[i][j][q] = 0.f;

    gemm_core(sbase, m0, n0, tid, Ah, Al, Bh, Bl, acc);

    const int wid = tid >> 5, lane = tid & 31;
    const int m_w = (wid >> 1) * 32, n_w = (wid & 1) * 64;
    const int g = lane >> 2, qn = (lane & 3) * 2;
#pragma unroll
    for (int mi = 0; mi < 2; ++mi) {
#pragma unroll
        for (int h = 0; h < 2; ++h) {
            const int row = m0 + m_w + mi * 16 + g + h * 8;
            const int b_ = row >> 11, s_ = row & (SS - 1);
            const size_t base = ((size_t)((b_ * NHD + blockIdx.x) * SS + s_)) * HDD;
#pragma unroll
            for (int nf = 0; nf < 8; ++nf) {
                const int col = n_w + nf * 8 + qn;
                const float v0 = alpha * (acc[mi][nf][h * 2 + 0] + bias[n0 + col]);
                const float v1 = alpha * (acc[mi][nf][h * 2 + 1] + bias[n0 + col + 1]);
                const float r0f = v0 - __bfloat162float(__float2bfloat16(v0));
                const float r1f = v1 - __bfloat162float(__float2bfloat16(v1));
                *(uint32_t*)(Ch + base + col) = pack_bf16(v0, v1);
                *(uint32_t*)(Cl + base + col) = pack_bf16(r0f, r1f);
            }
        }
    }
}

// ---- O-projection GEMM: fp32 row-major out ----
__global__ void __launch_bounds__(256, 2) gemm_out(
    const __nv_bfloat16* __restrict__ Ah, const __nv_bfloat16* __restrict__ Al,
    const __nv_bfloat16* __restrict__ Bh, const __nv_bfloat16* __restrict__ Bl,
    const float* __restrict__ bias, float* __restrict__ C)
{
    extern __shared__ char sm8[];
    const uint32_t sbase = smem_u32(sm8);
    const int tid = threadIdx.x;
    const int m0 = blockIdx.y * 128, n0 = blockIdx.x * 128;

    float acc[2][8][4];
#pragma unroll
    for (int i = 0; i < 2; i++)
#pragma unroll
        for (int j = 0; j < 8; j++)
#pragma unroll
            for (int q = 0; q < 4; q++) acc[i][j][q] = 0.f;

    gemm_core(sbase, m0, n0, tid, Ah, Al, Bh, Bl, acc);

    const int wid = tid >> 5, lane = tid & 31;
    const int m_w = (wid >> 1) * 32, n_w = (wid & 1) * 64;
    const int g = lane >> 2, qn = (lane & 3) * 2;
#pragma unroll
    for (int mi = 0; mi < 2; ++mi) {
#pragma unroll
        for (int h = 0; h < 2; ++h) {
            const int row = m0 + m_w + mi * 16 + g + h * 8;
            float* dst = C + (size_t)row * HH + n0;
#pragma unroll
            for (int nf = 0; nf < 8; ++nf) {
                const int col = n_w + nf * 8 + qn;
                float2 ov;
                ov.x = acc[mi][nf][h * 2 + 0] + bias[n0 + col];
                ov.y = acc[mi][nf][h * 2 + 1] + bias[n0 + col + 1];
                *(float2*)(dst + col) = ov;
            }
        }
    }
}

// ======================= mma.sync flash attention (complement-of-window mask) =======================
// masked (excluded) iff 0 <= qi - kj < W.  Fully-masked 128-tiles: (i0>>7) - jt in {1,2,3}.
#define AT_STRIDE 272                    // bytes per smem row (128 bf16 + 16B pad)
#define AT_MAT    (128 * AT_STRIDE)      // 34816
#define AT_SMEM   (6 * AT_MAT)           // 208896

__device__ __forceinline__ void attn_load(uint32_t dst, const __nv_bfloat16* __restrict__ g,
                                          int row0, int tid)
{
    const __nv_bfloat16* gp = g + (size_t)row0 * HDD;
#pragma unroll
    for (int i = 0; i < 8; i++) {
        const int idx = tid + i * 256;
        const int r = idx >> 4, c = idx & 15;
        cp_async16(dst + r * AT_STRIDE + c * 16, gp + r * HDD + c * 8);
    }
}

__global__ void __launch_bounds__(256) attn_mma()
{
    extern __shared__ char smx[];
    const uint32_t sb = smem_u32(smx);
    const uint32_t Qh = sb,              Ql = sb + 1 * AT_MAT;
    const uint32_t Kh = sb + 2 * AT_MAT, Kl = sb + 3 * AT_MAT;
    const uint32_t Vh = sb + 4 * AT_MAT, Vl = sb + 5 * AT_MAT;

    const int i0 = blockIdx.x * 128;
    const int head = blockIdx.y;
    const int b = blockIdx.z;
    const size_t hb = (size_t)(b * NHD + head) * SS * HDD;
    const __nv_bfloat16 *qhB = g_qh + hb, *qlB = g_ql + hb;
    const __nv_bfloat16 *khB = g_kh + hb, *klB = g_kl + hb;
    const __nv_bfloat16 *vhB = g_vh + hb, *vlB = g_vl + hb;

    const int tid = threadIdx.x, wid = tid >> 5, lane = tid & 31;
    const int arow = lane & 15, khalf16 = (lane >> 4) * 16;   // byte offset half
    const int g = lane >> 2, q = lane & 3;
    const int row0 = i0 + wid * 16 + g;            // second row = row0 + 8

    // list of non-fully-masked key tiles
    int tiles[16]; int nt = 0;
    const int bi = i0 >> 7;
#pragma unroll
    for (int jt = 0; jt < 16; jt++) {
        const int d = bi - jt;
        if (d != 1 && d != 2 && d != 3) tiles[nt++] = jt;
    }

    // prologue loads: Q + K(t0) in group 0; V(t0) in group 1
    attn_load(Qh, qhB, i0, tid);
    attn_load(Ql, qlB, i0, tid);
    attn_load(Kh, khB, tiles[0] * 128, tid);
    attn_load(Kl, klB, tiles[0] * 128, tid);
    cp_commit();
    attn_load(Vh, vhB, tiles[0] * 128, tid);
    attn_load(Vl, vlB, tiles[0] * 128, tid);
    cp_commit();

    float o[16][4];
#pragma unroll
    for (int t = 0; t < 16; t++)
#pragma unroll
        for (int c = 0; c < 4; c++) o[t][c] = 0.f;
    float m0 = NEG_INF, m1 = NEG_INF, l0 = 0.f, l1 = 0.f;

    uint32_t qh4[8][4], ql4[8][4];     // Q fragments, loaded once at ti==0

    for (int ti = 0; ti < nt; ti++) {
        const int j0 = tiles[ti] * 128;

        cp_wait<1>();          // K(ti) (+Q on first iter) ready
        __syncthreads();

        if (ti == 0) {
            // hoist Q fragments into registers (reused for all tiles)
#pragma unroll
            for (int ks = 0; ks < 8; ks++) {
                const uint32_t aoff = (wid * 16 + arow) * AT_STRIDE + ks * 32 + khalf16;
                ldm_x4(qh4[ks][0], qh4[ks][1], qh4[ks][2], qh4[ks][3], Qh + aoff);
                ldm_x4(ql4[ks][0], ql4[ks][1], ql4[ks][2], ql4[ks][3], Ql + aoff);
            }
        }

        // ---- S = Q K^T (3-term split) ----
        float s[16][4];
#pragma unroll
        for (int t = 0; t < 16; t++)
#pragma unroll
            for (int c = 0; c < 4; c++) s[t][c] = 0.f;

#pragma unroll
        for (int ks = 0; ks < 8; ks++) {
            const uint32_t kb = ks * 32 + khalf16;
#pragma unroll
            for (int nf = 0; nf < 8; nf++) {
                const uint32_t roff = (nf * 16 + arow) * AT_STRIDE + kb;
                uint32_t r0, r1, r2, r3, u0, u1, u2, u3;
                ldm_x4(r0, r1, r2, r3, Kh + roff);
                ldm_x4(u0, u1, u2, u3, Kl + roff);
                uint32_t bh0[2] = {r0, r2}, bh1[2] = {r1, r3};
                uint32_t bl0[2] = {u0, u2}, bl1[2] = {u1, u3};
                mma16816(s[2 * nf], qh4[ks], bh0);
                mma16816(s[2 * nf], qh4[ks], bl0);
                mma16816(s[2 * nf], ql4[ks], bh0);
                mma16816(s[2 * nf + 1], qh4[ks], bh1);
                mma16816(s[2 * nf + 1], qh4[ks], bl1);
                mma16816(s[2 * nf + 1], ql4[ks], bh1);
            }
        }

        // ---- mask + online softmax (warp-local; rows row0, row0+8) ----
#pragma unroll
        for (int t = 0; t < 16; t++) {
            const int kj = j0 + 8 * t + 2 * q;
#pragma unroll
            for (int c = 0; c < 4; c++) {
                const int qi = (c < 2) ? row0 : row0 + 8;
                const int dl = qi - (kj + (c & 1));
                if (dl >= 0 && dl < WW) s[t][c] = NEG_INF;
            }
        }
        float rm0 = NEG_INF, rm1 = NEG_INF;
#pragma unroll
        for (int t = 0; t < 16; t++) {
            rm0 = fmaxf(rm0, fmaxf(s[t][0], s[t][1]));
            rm1 = fmaxf(rm1, fmaxf(s[t][2], s[t][3]));
        }
        rm0 = fmaxf(rm0, __shfl_xor_sync(0xffffffffu, rm0, 1));
        rm0 = fmaxf(rm0, __shfl_xor_sync(0xffffffffu, rm0, 2));
        rm1 = fmaxf(rm1, __shfl_xor_sync(0xffffffffu, rm1, 1));
        rm1 = fmaxf(rm1, __shfl_xor_sync(0xffffffffu, rm1, 2));
        const float mn0 = fmaxf(m0, rm0), mn1 = fmaxf(m1, rm1);
        const float c0 = (m0 == mn0) ? 1.f : __expf(m0 - mn0);
        const float c1 = (m1 == mn1) ? 1.f : __expf(m1 - mn1);
        float sum0 = 0.f, sum1 = 0.f;
#pragma unroll
        for (int t = 0; t < 16; t++) {
#pragma unroll
            for (int c = 0; c < 4; c++) {
                const float sv = s[t][c];
                const float mn = (c < 2) ? mn0 : mn1;
                const float p = (sv == NEG_INF) ? 0.f : __expf(sv - mn);
                s[t][c] = p;
                if (c < 2) sum0 += p; else sum1 += p;
            }
        }
        sum0 += __shfl_xor_sync(0xffffffffu, sum0, 1);
        sum0 += __shfl_xor_sync(0xffffffffu, sum0, 2);
        sum1 += __shfl_xor_sync(0xffffffffu, sum1, 1);
        sum1 += __shfl_xor_sync(0xffffffffu, sum1, 2);
        l0 = l0 * c0 + sum0; m0 = mn0;
        l1 = l1 * c1 + sum1; m1 = mn1;
#pragma unroll
        for (int t = 0; t < 16; t++) {
            o[t][0] *= c0; o[t][1] *= c0; o[t][2] *= c1; o[t][3] *= c1;
        }

        __syncthreads();       // all warps done reading K
        if (ti + 1 < nt) {
            const int jn = tiles[ti + 1] * 128;
            attn_load(Kh, khB, jn, tid);
            attn_load(Kl, klB, jn, tid);
        }
        cp_commit();           // K(ti+1) group (possibly empty)

        cp_wait<1>();          // V(ti) ready (pending: K(ti+1))
        __syncthreads();

        // ---- O += P V (3-term split; V fragments via ldmatrix.trans) ----
#pragma unroll
        for (int u = 0; u < 8; u++) {
            uint32_t ph[4], pl[4];
            {
                const float p00 = s[2 * u][0],     p01 = s[2 * u][1];
                const float p02 = s[2 * u][2],     p03 = s[2 * u][3];
                const float p10 = s[2 * u + 1][0], p11 = s[2 * u + 1][1];
                const float p12 = s[2 * u + 1][2], p13 = s[2 * u + 1][3];
                ph[0] = pack_bf16(p00, p01);
                ph[1] = pack_bf16(p02, p03);
                ph[2] = pack_bf16(p10, p11);
                ph[3] = pack_bf16(p12, p13);
                pl[0] = pack_bf16(p00 - __bfloat162float(__float2bfloat16(p00)),
                                  p01 - __bfloat162float(__float2bfloat16(p01)));
                pl[1] = pack_bf16(p02 - __bfloat162float(__float2bfloat16(p02)),
                                  p03 - __bfloat162float(__float2bfloat16(p03)));
                pl[2] = pack_bf16(p10 - __bfloat162float(__float2bfloat16(p10)),
                                  p11 - __bfloat162float(__float2bfloat16(p11)));
                pl[3] = pack_bf16(p12 - __bfloat162float(__float2bfloat16(p12)),
                                  p13 - __bfloat162float(__float2bfloat16(p13)));
            }
#pragma unroll
            for (int dp = 0; dp < 8; dp++) {
                const uint32_t roff = (u * 16 + arow) * AT_STRIDE + dp * 32 + khalf16;
                uint32_t r0, r1, r2, r3, u0, u1, u2, u3;
                ldm_x4t(r0, r1, r2, r3, Vh + roff);
                ldm_x4t(u0, u1, u2, u3, Vl + roff);
                uint32_t bvh0[2] = {r0, r1}, bvh1[2] = {r2, r3};
                uint32_t bvl0[2] = {u0, u1}, bvl1[2] = {u2, u3};
                mma16816(o[2 * dp], ph, bvh0);
                mma16816(o[2 * dp], ph, bvl0);
                mma16816(o[2 * dp], pl, bvh0);
                mma16816(o[2 * dp + 1], ph, bvh1);
                mma16816(o[2 * dp + 1], ph, bvl1);
                mma16816(o[2 * dp + 1], pl, bvh1);
            }
        }

        __syncthreads();       // all warps done reading V
        if (ti + 1 < nt) {
            const int jn = tiles[ti + 1] * 128;
            attn_load(Vh, vhB, jn, tid);
            attn_load(Vl, vlB, jn, tid);
        }
        cp_commit();           // V(ti+1) group (possibly empty)
    }

    // ---- epilogue: normalize, split hi/lo, write [B,S,NH,HD] ----
    const float inv0 = 1.f / l0, inv1 = 1.f / l1;
    const size_t base0 = ((size_t)(b * SS + row0) * NHD + head) * HDD;
    const size_t base1 = base0 + (size_t)8 * NHD * HDD;
#pragma unroll
    for (int t = 0; t < 16; t++) {
        const int d = 8 * t + 2 * q;
        const float f0 = o[t][0] * inv0, f1 = o[t][1] * inv0;
        const float f2 = o[t][2] * inv1, f3 = o[t][3] * inv1;
        *(uint32_t*)(g_aoh + base0 + d) = pack_bf16(f0, f1);
        *(uint32_t*)(g_aol + base0 + d) =
            pack_bf16(f0 - __bfloat162float(__float2bfloat16(f0)),
                      f1 - __bfloat162float(__float2bfloat16(f1)));
        *(uint32_t*)(g_aoh + base1 + d) = pack_bf16(f2, f3);
        *(uint32_t*)(g_aol + base1 + d) =
            pack_bf16(f2 - __bfloat162float(__float2bfloat16(f2)),
                      f3 - __bfloat162float(__float2bfloat16(f3)));
    }
}

// ======================= launch =======================
extern "C" void kernel_launch(void* const* d_in, const int* in_sizes, int n_in,
                              void* d_out, int out_size)
{
    (void)in_sizes; (void)n_in; (void)out_size;
    const float* x   = (const float*)d_in[0];
    const float* lns = (const float*)d_in[1];
    const float* lnb = (const float*)d_in[2];
    const float* wq  = (const float*)d_in[3];
    const float* bq  = (const float*)d_in[4];
    const float* wk  = (const float*)d_in[5];
    const float* bk  = (const float*)d_in[6];
    const float* wv  = (const float*)d_in[7];
    const float* bv  = (const float*)d_in[8];
    const float* wo  = (const float*)d_in[9];
    const float* bo  = (const float*)d_in[10];
    float* out = (float*)d_out;

    __nv_bfloat16 *pyh, *pyl, *pwqh, *pwql, *pwkh, *pwkl, *pwvh, *pwvl, *pwoh, *pwol;
    __nv_bfloat16 *pqh, *pql, *pkh, *pkl, *pvh, *pvl, *paoh, *paol;
    cudaGetSymbolAddress((void**)&pyh, g_yh);   cudaGetSymbolAddress((void**)&pyl, g_yl);
    cudaGetSymbolAddress((void**)&pwqh, g_wqh); cudaGetSymbolAddress((void**)&pwql, g_wql);
    cudaGetSymbolAddress((void**)&pwkh, g_wkh); cudaGetSymbolAddress((void**)&pwkl, g_wkl);
    cudaGetSymbolAddress((void**)&pwvh, g_wvh); cudaGetSymbolAddress((void**)&pwvl, g_wvl);
    cudaGetSymbolAddress((void**)&pwoh, g_woh); cudaGetSymbolAddress((void**)&pwol, g_wol);
    cudaGetSymbolAddress((void**)&pqh, g_qh);   cudaGetSymbolAddress((void**)&pql, g_ql);
    cudaGetSymbolAddress((void**)&pkh, g_kh);   cudaGetSymbolAddress((void**)&pkl, g_kl);
    cudaGetSymbolAddress((void**)&pvh, g_vh);   cudaGetSymbolAddress((void**)&pvl, g_vl);
    cudaGetSymbolAddress((void**)&paoh, g_aoh); cudaGetSymbolAddress((void**)&paol, g_aol);

    ln_kernel<<<BSZ, 256>>>(x, lns, lnb, pyh, pyl);

    wsplit_all<<<dim3(HH / 32, HH / 32, 4), 256>>>(
        wq, wk, wv, wo, pwqh, pwql, pwkh, pwkl, pwvh, pwvl, pwoh, pwol);

    cudaFuncSetAttribute(gemm_qkv, cudaFuncAttributeMaxDynamicSharedMemorySize, GP_SMEM);
    cudaFuncSetAttribute(gemm_out, cudaFuncAttributeMaxDynamicSharedMemorySize, GP_SMEM);

    gemm_qkv<<<dim3(HH / 128, BSZ / 128, 3), 256, GP_SMEM>>>(
        pyh, pyl, pwqh, pwql, pwkh, pwkl, pwvh, pwvl,
        bq, bk, bv, pqh, pql, pkh, pkl, pvh, pvl);

    cudaFuncSetAttribute(attn_mma, cudaFuncAttributeMaxDynamicSharedMemorySize, AT_SMEM);
    attn_mma<<<dim3(SS / 128, NHD, BB), 256, AT_SMEM>>>();

    gemm_out<<<dim3(HH / 128, BSZ / 128), 256, GP_SMEM>>>(paoh, paol, pwoh, pwol, bo, out);
}